// round 3
// baseline (speedup 1.0000x reference)
#include <cuda_runtime.h>
#include <cstdint>
#include <cstddef>

#define BB 32
#define SS 576
#define DD 768
#define HH 12
#define HDD 64
#define MTOK (BB*SS)               // 18432
#define OUT_ELEMS (BB*SS*DD)       // 14155776
#define ATTN_ELEMS (BB*HH*SS*SS)   // 127401984
#define SCALE 0.125f

// ---- scratch (static device globals; no runtime allocation) ----
__device__ float g_q[OUT_ELEMS];
__device__ float g_k[OUT_ELEMS];
__device__ float g_v[OUT_ELEMS];
__device__ float g_ctx[OUT_ELEMS];
__device__ float g_xr[OUT_ELEMS];          // tf32-rounded x
__device__ float g_attn_fallback[ATTN_ELEMS];

// ---------------------------------------------------------------------------
__device__ __forceinline__ float rna_tf32(float x) {
    unsigned u;
    asm("cvt.rna.tf32.f32 %0, %1;" : "=r"(u) : "f"(x));
    return __uint_as_float(u);
}

__device__ __forceinline__ void mma_tf32(float c[4],
    uint32_t a0, uint32_t a1, uint32_t a2, uint32_t a3,
    uint32_t b0, uint32_t b1)
{
    asm volatile(
        "mma.sync.aligned.m16n8k8.row.col.f32.tf32.tf32.f32 "
        "{%0,%1,%2,%3}, {%4,%5,%6,%7}, {%8,%9}, {%0,%1,%2,%3};"
        : "+f"(c[0]), "+f"(c[1]), "+f"(c[2]), "+f"(c[3])
        : "r"(a0), "r"(a1), "r"(a2), "r"(a3), "r"(b0), "r"(b1));
}

__device__ __forceinline__ void cpa16(void* dst, const void* src) {
    uint32_t d = (uint32_t)__cvta_generic_to_shared(dst);
    asm volatile("cp.async.cg.shared.global [%0], [%1], 16;\n"
                 :: "r"(d), "l"(src));
}

// ---------------------------------------------------------------------------
// elementwise tf32 rounding pass (float4, grid-stride), n divisible by 4
__global__ void round_tf32_kernel(const float* __restrict__ in,
                                  float* __restrict__ out, int n4)
{
    for (int i = blockIdx.x * blockDim.x + threadIdx.x; i < n4;
         i += gridDim.x * blockDim.x) {
        float4 v = ((const float4*)in)[i];
        v.x = rna_tf32(v.x); v.y = rna_tf32(v.y);
        v.z = rna_tf32(v.z); v.w = rna_tf32(v.w);
        ((float4*)out)[i] = v;
    }
}

// ---------------------------------------------------------------------------
// GEMM body: C[M,N] = A[M,K] @ W^T + bias.
// A pre-rounded tf32; W raw fp32 (rounded in fragment load).
// BM=128, BN=128, BK=32, 256 threads, tf32 mma, cp.async double buffer.
// Dynamic smem: 4*128*36 floats = 73728 bytes.
// ---------------------------------------------------------------------------
#define GS (128*36)

__device__ __forceinline__ void gemm_body(
    const float* __restrict__ A, const float* __restrict__ W,
    const float* __restrict__ bias, float* __restrict__ C,
    int N, int K)
{
    extern __shared__ float dsm[];

    const int tid = threadIdx.x;
    const int m0 = blockIdx.y * 128;
    const int n0 = blockIdx.x * 128;
    const int warp = tid >> 5;
    const int lane = tid & 31;
    const int g = lane >> 2;
    const int t = lane & 3;
    const int warpm = warp >> 2;  // 0..1
    const int warpn = warp & 3;   // 0..3

    float acc[4][4][4];
    #pragma unroll
    for (int i = 0; i < 4; i++)
        #pragma unroll
        for (int j = 0; j < 4; j++)
            #pragma unroll
            for (int r = 0; r < 4; r++) acc[i][j][r] = 0.f;

    auto load_stage = [&](int st, int k0) {
        float* as = dsm + st * GS;
        float* bs = dsm + 2 * GS + st * GS;
        #pragma unroll
        for (int i = 0; i < 4; i++) {
            int c = tid + i * 256;          // float4 idx in [0,1024)
            int row = c >> 3, seg = c & 7;  // 8 float4 per 32-wide row
            cpa16(&as[row*36 + seg*4], &A[(size_t)(m0 + row) * K + k0 + seg*4]);
        }
        #pragma unroll
        for (int i = 0; i < 4; i++) {
            int c = tid + i * 256;
            int row = c >> 3, seg = c & 7;
            cpa16(&bs[row*36 + seg*4], &W[(size_t)(n0 + row) * K + k0 + seg*4]);
        }
    };

    const int iters = K / 32;
    load_stage(0, 0);
    asm volatile("cp.async.commit_group;\n" ::);

    for (int it = 0; it < iters; ++it) {
        int s = it & 1;
        if (it + 1 < iters) load_stage(s ^ 1, (it + 1) * 32);
        asm volatile("cp.async.commit_group;\n" ::);
        asm volatile("cp.async.wait_group 1;\n" ::);
        __syncthreads();

        const float* as = dsm + s * GS;
        const float* bs = dsm + 2 * GS + s * GS;
        #pragma unroll
        for (int ks = 0; ks < 4; ks++) {
            int k = ks * 8;
            uint32_t af[4][4];
            #pragma unroll
            for (int ms = 0; ms < 4; ms++) {
                const float* p = as + (warpm*64 + ms*16 + g) * 36 + k + t;
                af[ms][0] = __float_as_uint(p[0]);
                af[ms][1] = __float_as_uint(p[8*36]);
                af[ms][2] = __float_as_uint(p[4]);
                af[ms][3] = __float_as_uint(p[8*36 + 4]);
            }
            #pragma unroll
            for (int ns = 0; ns < 4; ns++) {
                const float* p = bs + (warpn*32 + ns*8 + g) * 36 + k + t;
                uint32_t b0 = __float_as_uint(rna_tf32(p[0]));
                uint32_t b1 = __float_as_uint(rna_tf32(p[4]));
                #pragma unroll
                for (int ms = 0; ms < 4; ms++)
                    mma_tf32(acc[ms][ns], af[ms][0], af[ms][1], af[ms][2],
                             af[ms][3], b0, b1);
            }
        }
        __syncthreads();
    }

    #pragma unroll
    for (int ms = 0; ms < 4; ms++) {
        int row0 = m0 + warpm*64 + ms*16 + g;
        #pragma unroll
        for (int ns = 0; ns < 4; ns++) {
            int col = n0 + warpn*32 + ns*8 + 2*t;
            float b0v = bias[col], b1v = bias[col + 1];
            float2 v0 = {acc[ms][ns][0] + b0v, acc[ms][ns][1] + b1v};
            *(float2*)&C[(size_t)row0 * N + col] = v0;
            float2 v1 = {acc[ms][ns][2] + b0v, acc[ms][ns][3] + b1v};
            *(float2*)&C[(size_t)(row0 + 8) * N + col] = v1;
        }
    }
}

// fused Q/K/V projection: blockIdx.z selects weights/output
__global__ __launch_bounds__(256) void gemm_qkv(
    const float* __restrict__ A,
    const float* __restrict__ Wq, const float* __restrict__ Wk,
    const float* __restrict__ Wv,
    const float* __restrict__ bq, const float* __restrict__ bk,
    const float* __restrict__ bv,
    float* __restrict__ Cq, float* __restrict__ Ck, float* __restrict__ Cv)
{
    int z = blockIdx.z;
    const float* W    = (z == 0) ? Wq : (z == 1) ? Wk : Wv;
    const float* bias = (z == 0) ? bq : (z == 1) ? bk : bv;
    float*       C    = (z == 0) ? Cq : (z == 1) ? Ck : Cv;
    gemm_body(A, W, bias, C, DD, DD);
}

__global__ __launch_bounds__(256) void gemm_single(
    const float* __restrict__ A, const float* __restrict__ W,
    const float* __restrict__ bias, float* __restrict__ C)
{
    gemm_body(A, W, bias, C, DD, DD);
}

// ---------------------------------------------------------------------------
// Fused attention per (b, h, 64-query tile):
//   scores (tf32 mma) -> softmax (probs stay in smem) -> attn write -> AV mma
// smem: qs[64][68], ks[64][68], sc[64][580]; V tiles reuse qs/ks region.
// ---------------------------------------------------------------------------
#define SCQ 68
#define SCS 580
#define VSS 72
#define ATTN_SMEM_FLOATS (2*64*SCQ + 64*SCS)   // 45824 floats

__global__ __launch_bounds__(256) void attn_fused(
    const float* __restrict__ Q, const float* __restrict__ K,
    const float* __restrict__ V, float* __restrict__ attn,
    float* __restrict__ ctx)
{
    extern __shared__ float smem[];
    float* qs = smem;                    // [64][SCQ]
    float* ks = smem + 64*SCQ;           // [64][SCQ]
    float* sc = smem + 2*64*SCQ;         // [64][SCS]
    float* vs = smem;                    // [64][VSS], reuses qs/ks after scores

    const int qt = blockIdx.x, h = blockIdx.y, b = blockIdx.z;
    const int s0 = qt * 64;
    const int tid = threadIdx.x;
    const int warp = tid >> 5;
    const int lane = tid & 31;
    const int g = lane >> 2, t = lane & 3;
    const int warpm = warp >> 2;   // 0..1
    const int warpn = warp & 3;    // 0..3

    // ---- load Q tile (tf32-rounded) ----
    #pragma unroll
    for (int i = 0; i < 4; i++) {
        int idx = tid + i * 256;
        int qi = idx >> 4, d4 = idx & 15;
        float4 v = *(const float4*)&Q[((size_t)(b*SS + s0 + qi))*DD + h*HDD + d4*4];
        float* p = qs + qi*SCQ + d4*4;
        p[0] = rna_tf32(v.x); p[1] = rna_tf32(v.y);
        p[2] = rna_tf32(v.z); p[3] = rna_tf32(v.w);
    }

    // ---- scores: QK^T into sc strip ----
    for (int kt = 0; kt < SS/64; kt++) {
        __syncthreads();
        #pragma unroll
        for (int i = 0; i < 4; i++) {
            int idx = tid + i * 256;
            int kj = idx >> 4, d4 = idx & 15;
            float4 v = *(const float4*)&K[((size_t)(b*SS + kt*64 + kj))*DD + h*HDD + d4*4];
            float* p = ks + kj*SCQ + d4*4;
            p[0] = rna_tf32(v.x); p[1] = rna_tf32(v.y);
            p[2] = rna_tf32(v.z); p[3] = rna_tf32(v.w);
        }
        __syncthreads();

        float acc[2][2][4];
        #pragma unroll
        for (int i = 0; i < 2; i++)
            #pragma unroll
            for (int j = 0; j < 2; j++)
                #pragma unroll
                for (int r = 0; r < 4; r++) acc[i][j][r] = 0.f;

        #pragma unroll
        for (int kk = 0; kk < 8; kk++) {
            int k = kk * 8;
            uint32_t af[2][4];
            #pragma unroll
            for (int ms = 0; ms < 2; ms++) {
                const float* p = qs + (warpm*32 + ms*16 + g)*SCQ + k + t;
                af[ms][0] = __float_as_uint(p[0]);
                af[ms][1] = __float_as_uint(p[8*SCQ]);
                af[ms][2] = __float_as_uint(p[4]);
                af[ms][3] = __float_as_uint(p[8*SCQ + 4]);
            }
            #pragma unroll
            for (int ns = 0; ns < 2; ns++) {
                const float* p = ks + (warpn*16 + ns*8 + g)*SCQ + k + t;
                uint32_t b0 = __float_as_uint(p[0]);
                uint32_t b1 = __float_as_uint(p[4]);
                #pragma unroll
                for (int ms = 0; ms < 2; ms++)
                    mma_tf32(acc[ms][ns], af[ms][0], af[ms][1], af[ms][2],
                             af[ms][3], b0, b1);
            }
        }

        #pragma unroll
        for (int ms = 0; ms < 2; ms++) {
            int row = warpm*32 + ms*16 + g;
            #pragma unroll
            for (int ns = 0; ns < 2; ns++) {
                int col = kt*64 + warpn*16 + ns*8 + 2*t;
                float2 v0 = {acc[ms][ns][0]*SCALE, acc[ms][ns][1]*SCALE};
                *(float2*)&sc[row*SCS + col] = v0;
                float2 v1 = {acc[ms][ns][2]*SCALE, acc[ms][ns][3]*SCALE};
                *(float2*)&sc[(row+8)*SCS + col] = v1;
            }
        }
    }
    __syncthreads();

    // ---- softmax: 8 warps x 8 rows; write attn to gmem, rounded probs to sc
    for (int r = warp*8; r < warp*8 + 8; r++) {
        float mx = -1e30f;
        for (int j = lane; j < SS; j += 32) mx = fmaxf(mx, sc[r*SCS + j]);
        #pragma unroll
        for (int o = 16; o; o >>= 1) mx = fmaxf(mx, __shfl_xor_sync(0xffffffffu, mx, o));
        float sum = 0.f;
        for (int j = lane; j < SS; j += 32) {
            float e = __expf(sc[r*SCS + j] - mx);
            sc[r*SCS + j] = e;
            sum += e;
        }
        #pragma unroll
        for (int o = 16; o; o >>= 1) sum += __shfl_xor_sync(0xffffffffu, sum, o);
        float inv = 1.f / sum;
        float* dst = attn + (((size_t)b*HH + h)*SS + s0 + r) * (size_t)SS;
        for (int j = lane; j < SS; j += 32) {
            float p = sc[r*SCS + j] * inv;
            dst[j] = p;                       // full-precision attn output
            sc[r*SCS + j] = rna_tf32(p);      // tf32 for AV mma
        }
    }
    __syncthreads();

    // ---- AV: ctx = probs @ V, V tiles streamed into vs ----
    float acc[2][2][4];
    #pragma unroll
    for (int i = 0; i < 2; i++)
        #pragma unroll
        for (int j = 0; j < 2; j++)
            #pragma unroll
            for (int r = 0; r < 4; r++) acc[i][j][r] = 0.f;

    for (int kt = 0; kt < SS/64; kt++) {
        #pragma unroll
        for (int i = 0; i < 4; i++) {
            int idx = tid + i * 256;
            int kk = idx >> 4, n4 = idx & 15;
            float4 v = *(const float4*)&V[((size_t)(b*SS + kt*64 + kk))*DD + h*HDD + n4*4];
            float* p = vs + kk*VSS + n4*4;
            p[0] = rna_tf32(v.x); p[1] = rna_tf32(v.y);
            p[2] = rna_tf32(v.z); p[3] = rna_tf32(v.w);
        }
        __syncthreads();

        #pragma unroll
        for (int kk = 0; kk < 8; kk++) {
            int k = kk * 8;
            uint32_t af[2][4];
            #pragma unroll
            for (int ms = 0; ms < 2; ms++) {
                const float* p = sc + (warpm*32 + ms*16 + g)*SCS + kt*64 + k + t;
                af[ms][0] = __float_as_uint(p[0]);
                af[ms][1] = __float_as_uint(p[8*SCS]);
                af[ms][2] = __float_as_uint(p[4]);
                af[ms][3] = __float_as_uint(p[8*SCS + 4]);
            }
            #pragma unroll
            for (int ns = 0; ns < 2; ns++) {
                int nb = warpn*16 + ns*8;
                uint32_t b0 = __float_as_uint(vs[(k + t)*VSS + nb + g]);
                uint32_t b1 = __float_as_uint(vs[(k + t + 4)*VSS + nb + g]);
                #pragma unroll
                for (int ms = 0; ms < 2; ms++)
                    mma_tf32(acc[ms][ns], af[ms][0], af[ms][1], af[ms][2],
                             af[ms][3], b0, b1);
            }
        }
        __syncthreads();
    }

    // ---- ctx epilogue (tf32-rounded; feeds final GEMM as A) ----
    #pragma unroll
    for (int ms = 0; ms < 2; ms++) {
        int row = warpm*32 + ms*16 + g;
        #pragma unroll
        for (int ns = 0; ns < 2; ns++) {
            int col = warpn*16 + ns*8 + 2*t;
            float2 v0 = {rna_tf32(acc[ms][ns][0]), rna_tf32(acc[ms][ns][1])};
            *(float2*)&ctx[((size_t)(b*SS + s0 + row))*DD + h*HDD + col] = v0;
            float2 v1 = {rna_tf32(acc[ms][ns][2]), rna_tf32(acc[ms][ns][3])};
            *(float2*)&ctx[((size_t)(b*SS + s0 + row + 8))*DD + h*HDD + col] = v1;
        }
    }
}

// ===========================================================================
extern "C" void kernel_launch(void* const* d_in, const int* in_sizes, int n_in,
                              void* d_out, int out_size)
{
    const float* x  = (const float*)d_in[0];
    const float* Wq = (const float*)d_in[1];
    const float* bq = (const float*)d_in[2];
    const float* Wk = (const float*)d_in[3];
    const float* bk = (const float*)d_in[4];
    const float* Wv = (const float*)d_in[5];
    const float* bv = (const float*)d_in[6];
    const float* Wo = (const float*)d_in[7];
    const float* bo = (const float*)d_in[8];

    float* out = (float*)d_out;
    float* attn;
    if (out_size >= OUT_ELEMS + ATTN_ELEMS) {
        attn = out + OUT_ELEMS;
    } else {
        void* p; cudaGetSymbolAddress(&p, g_attn_fallback);
        attn = (float*)p;
    }

    float *q, *k, *v, *ctx, *xr;
    { void* p; cudaGetSymbolAddress(&p, g_q);   q   = (float*)p; }
    { void* p; cudaGetSymbolAddress(&p, g_k);   k   = (float*)p; }
    { void* p; cudaGetSymbolAddress(&p, g_v);   v   = (float*)p; }
    { void* p; cudaGetSymbolAddress(&p, g_ctx); ctx = (float*)p; }
    { void* p; cudaGetSymbolAddress(&p, g_xr);  xr  = (float*)p; }

    const int gemm_smem = 4 * GS * (int)sizeof(float);      // 73728
    cudaFuncSetAttribute(gemm_qkv,
                         cudaFuncAttributeMaxDynamicSharedMemorySize, gemm_smem);
    cudaFuncSetAttribute(gemm_single,
                         cudaFuncAttributeMaxDynamicSharedMemorySize, gemm_smem);
    const int attn_smem = ATTN_SMEM_FLOATS * (int)sizeof(float);  // 183296
    cudaFuncSetAttribute(attn_fused,
                         cudaFuncAttributeMaxDynamicSharedMemorySize, attn_smem);

    // 1) round x to tf32
    round_tf32_kernel<<<1184, 256>>>(x, xr, OUT_ELEMS/4);

    // 2) fused Q/K/V projections
    dim3 gQKV(DD/128, MTOK/128, 3);       // (6, 144, 3)
    gemm_qkv<<<gQKV, 256, gemm_smem>>>(xr, Wq, Wk, Wv, bq, bk, bv, q, k, v);

    // 3) fused scores + softmax + AV
    dim3 gAttn(SS/64, HH, BB);            // (9, 12, 32)
    attn_fused<<<gAttn, 256, attn_smem>>>(q, k, v, attn, ctx);

    // 4) output projection
    dim3 gO(DD/128, MTOK/128);
    gemm_single<<<gO, 256, gemm_smem>>>(ctx, Wo, bo, out);
}

// round 4
// speedup vs baseline: 1.2022x; 1.2022x over previous
#include <cuda_runtime.h>
#include <cstdint>
#include <cstddef>

#define BB 32
#define SS 576
#define DD 768
#define HH 12
#define HDD 64
#define MTOK (BB*SS)               // 18432
#define OUT_ELEMS (BB*SS*DD)       // 14155776
#define ATTN_ELEMS (BB*HH*SS*SS)   // 127401984
#define SCALE 0.125f

// ---- scratch (static device globals; no runtime allocation) ----
__device__ float g_q[OUT_ELEMS];
__device__ float g_k[OUT_ELEMS];
__device__ float g_v[OUT_ELEMS];
__device__ float g_ctx[OUT_ELEMS];
__device__ float g_xr[OUT_ELEMS];
__device__ float g_wq[DD*DD], g_wk[DD*DD], g_wv[DD*DD], g_wo[DD*DD];
__device__ float g_attn_fallback[ATTN_ELEMS];

// ---------------------------------------------------------------------------
__device__ __forceinline__ float rna_tf32(float x) {
    unsigned u;
    asm("cvt.rna.tf32.f32 %0, %1;" : "=r"(u) : "f"(x));
    return __uint_as_float(u);
}

__device__ __forceinline__ void mma_tf32(float c[4],
    uint32_t a0, uint32_t a1, uint32_t a2, uint32_t a3,
    uint32_t b0, uint32_t b1)
{
    asm volatile(
        "mma.sync.aligned.m16n8k8.row.col.f32.tf32.tf32.f32 "
        "{%0,%1,%2,%3}, {%4,%5,%6,%7}, {%8,%9}, {%0,%1,%2,%3};"
        : "+f"(c[0]), "+f"(c[1]), "+f"(c[2]), "+f"(c[3])
        : "r"(a0), "r"(a1), "r"(a2), "r"(a3), "r"(b0), "r"(b1));
}

__device__ __forceinline__ void cpa16(void* dst, const void* src) {
    uint32_t d = (uint32_t)__cvta_generic_to_shared(dst);
    asm volatile("cp.async.cg.shared.global [%0], [%1], 16;\n"
                 :: "r"(d), "l"(src));
}

// ---------------------------------------------------------------------------
__global__ void round_tf32_kernel(const float* __restrict__ in,
                                  float* __restrict__ out, int n4)
{
    for (int i = blockIdx.x * blockDim.x + threadIdx.x; i < n4;
         i += gridDim.x * blockDim.x) {
        float4 v = ((const float4*)in)[i];
        v.x = rna_tf32(v.x); v.y = rna_tf32(v.y);
        v.z = rna_tf32(v.z); v.w = rna_tf32(v.w);
        ((float4*)out)[i] = v;
    }
}

// ---------------------------------------------------------------------------
// GEMM: C[M,N] = A[M,K] @ W^T + bias.  A and W pre-rounded to tf32.
// BM=128, BN=128, BK=32, 256 threads, tf32 mma, cp.async double buffer.
// ---------------------------------------------------------------------------
#define GS (128*36)

__device__ __forceinline__ void gemm_body(
    const float* __restrict__ A, const float* __restrict__ W,
    const float* __restrict__ bias, float* __restrict__ C,
    int N, int K)
{
    extern __shared__ float dsm[];

    const int tid = threadIdx.x;
    const int m0 = blockIdx.y * 128;
    const int n0 = blockIdx.x * 128;
    const int warp = tid >> 5;
    const int lane = tid & 31;
    const int g = lane >> 2;
    const int t = lane & 3;
    const int warpm = warp >> 2;
    const int warpn = warp & 3;

    float acc[4][4][4];
    #pragma unroll
    for (int i = 0; i < 4; i++)
        #pragma unroll
        for (int j = 0; j < 4; j++)
            #pragma unroll
            for (int r = 0; r < 4; r++) acc[i][j][r] = 0.f;

    auto load_stage = [&](int st, int k0) {
        float* as = dsm + st * GS;
        float* bs = dsm + 2 * GS + st * GS;
        #pragma unroll
        for (int i = 0; i < 4; i++) {
            int c = tid + i * 256;
            int row = c >> 3, seg = c & 7;
            cpa16(&as[row*36 + seg*4], &A[(size_t)(m0 + row) * K + k0 + seg*4]);
        }
        #pragma unroll
        for (int i = 0; i < 4; i++) {
            int c = tid + i * 256;
            int row = c >> 3, seg = c & 7;
            cpa16(&bs[row*36 + seg*4], &W[(size_t)(n0 + row) * K + k0 + seg*4]);
        }
    };

    const int iters = K / 32;
    load_stage(0, 0);
    asm volatile("cp.async.commit_group;\n" ::);

    for (int it = 0; it < iters; ++it) {
        int s = it & 1;
        if (it + 1 < iters) load_stage(s ^ 1, (it + 1) * 32);
        asm volatile("cp.async.commit_group;\n" ::);
        asm volatile("cp.async.wait_group 1;\n" ::);
        __syncthreads();

        const float* as = dsm + s * GS;
        const float* bs = dsm + 2 * GS + s * GS;
        #pragma unroll
        for (int ks = 0; ks < 4; ks++) {
            int k = ks * 8;
            uint32_t af[4][4];
            #pragma unroll
            for (int ms = 0; ms < 4; ms++) {
                const float* p = as + (warpm*64 + ms*16 + g) * 36 + k + t;
                af[ms][0] = __float_as_uint(p[0]);
                af[ms][1] = __float_as_uint(p[8*36]);
                af[ms][2] = __float_as_uint(p[4]);
                af[ms][3] = __float_as_uint(p[8*36 + 4]);
            }
            #pragma unroll
            for (int ns = 0; ns < 4; ns++) {
                const float* p = bs + (warpn*32 + ns*8 + g) * 36 + k + t;
                uint32_t b0 = __float_as_uint(p[0]);
                uint32_t b1 = __float_as_uint(p[4]);
                #pragma unroll
                for (int ms = 0; ms < 4; ms++)
                    mma_tf32(acc[ms][ns], af[ms][0], af[ms][1], af[ms][2],
                             af[ms][3], b0, b1);
            }
        }
        __syncthreads();
    }

    #pragma unroll
    for (int ms = 0; ms < 4; ms++) {
        int row0 = m0 + warpm*64 + ms*16 + g;
        #pragma unroll
        for (int ns = 0; ns < 4; ns++) {
            int col = n0 + warpn*32 + ns*8 + 2*t;
            float b0v = bias[col], b1v = bias[col + 1];
            float2 v0 = {acc[ms][ns][0] + b0v, acc[ms][ns][1] + b1v};
            *(float2*)&C[(size_t)row0 * N + col] = v0;
            float2 v1 = {acc[ms][ns][2] + b0v, acc[ms][ns][3] + b1v};
            *(float2*)&C[(size_t)(row0 + 8) * N + col] = v1;
        }
    }
}

__global__ __launch_bounds__(256) void gemm_qkv(
    const float* __restrict__ A,
    const float* __restrict__ Wq, const float* __restrict__ Wk,
    const float* __restrict__ Wv,
    const float* __restrict__ bq, const float* __restrict__ bk,
    const float* __restrict__ bv,
    float* __restrict__ Cq, float* __restrict__ Ck, float* __restrict__ Cv)
{
    int z = blockIdx.z;
    const float* W    = (z == 0) ? Wq : (z == 1) ? Wk : Wv;
    const float* bias = (z == 0) ? bq : (z == 1) ? bk : bv;
    float*       C    = (z == 0) ? Cq : (z == 1) ? Ck : Cv;
    gemm_body(A, W, bias, C, DD, DD);
}

__global__ __launch_bounds__(256) void gemm_single(
    const float* __restrict__ A, const float* __restrict__ W,
    const float* __restrict__ bias, float* __restrict__ C)
{
    gemm_body(A, W, bias, C, DD, DD);
}

// ---------------------------------------------------------------------------
// Fused attention per (b, h, 32-query tile):
//   QK^T (tf32 mma, cp.async double-buffered 32-key stages) -> softmax
//   -> attn write -> AV (cp.async double-buffered V stages, overlaps softmax)
// smem: qs[32][68] | kv[2][32x72 buffers] | sc[32][580]  = 99 KB -> 2 CTA/SM
// ---------------------------------------------------------------------------
#define SCQ 68
#define SCK 68          // K stride inside kv buffer
#define VSS 72          // V stride inside kv buffer
#define KVPITCH (32*72) // per-stage buffer pitch (floats)
#define SCS 580
#define QROWS 32
#define NSTAGE (SS/32)  // 18
#define ATTN_SMEM_FLOATS (QROWS*SCQ + 2*KVPITCH + QROWS*SCS)  // 25344

__global__ __launch_bounds__(256) void attn_fused(
    const float* __restrict__ Q, const float* __restrict__ K,
    const float* __restrict__ V, float* __restrict__ attn,
    float* __restrict__ ctx)
{
    extern __shared__ float smem[];
    float* qs = smem;                        // [32][SCQ]
    float* kv = smem + QROWS*SCQ;            // 2 stage buffers
    float* sc = smem + QROWS*SCQ + 2*KVPITCH;// [32][SCS]

    const int qt = blockIdx.x, h = blockIdx.y, b = blockIdx.z;
    const int s0 = qt * QROWS;
    const int tid = threadIdx.x;
    const int warp = tid >> 5;
    const int lane = tid & 31;
    const int g = lane >> 2, t = lane & 3;
    const int warpm = warp >> 2;   // 0..1, 16 rows each
    const int warpn = warp & 3;    // 0..3

    const size_t kvbase = (size_t)b * SS * DD + h * HDD;

    // ---- load Q tile (rna to tf32): 32x64 = 512 float4, 2 per thread ----
    #pragma unroll
    for (int i = 0; i < 2; i++) {
        int c = tid + i * 256;
        int qi = c >> 4, d4 = c & 15;
        float4 v = *(const float4*)&Q[((size_t)(b*SS + s0 + qi))*DD + h*HDD + d4*4];
        float* p = qs + qi*SCQ + d4*4;
        p[0] = rna_tf32(v.x); p[1] = rna_tf32(v.y);
        p[2] = rna_tf32(v.z); p[3] = rna_tf32(v.w);
    }

    // cp.async loaders: 32 keys x 64 floats = 512 float4, 2 per thread
    auto load_k = [&](int st, int kt) {
        float* dst = kv + st * KVPITCH;
        #pragma unroll
        for (int i = 0; i < 2; i++) {
            int c = tid + i * 256;
            int row = c >> 4, seg = c & 15;
            cpa16(&dst[row*SCK + seg*4],
                  &K[kvbase + (size_t)(kt*32 + row)*DD + seg*4]);
        }
    };
    auto load_v = [&](int st, int kt) {
        float* dst = kv + st * KVPITCH;
        #pragma unroll
        for (int i = 0; i < 2; i++) {
            int c = tid + i * 256;
            int row = c >> 4, seg = c & 15;
            cpa16(&dst[row*VSS + seg*4],
                  &V[kvbase + (size_t)(kt*32 + row)*DD + seg*4]);
        }
    };

    // ---- scores: QK^T into sc strip, 18 double-buffered stages ----
    load_k(0, 0);
    asm volatile("cp.async.commit_group;\n" ::);

    for (int kt = 0; kt < NSTAGE; kt++) {
        int s = kt & 1;
        if (kt + 1 < NSTAGE) load_k(s ^ 1, kt + 1);
        asm volatile("cp.async.commit_group;\n" ::);
        asm volatile("cp.async.wait_group 1;\n" ::);
        __syncthreads();

        const float* ks = kv + s * KVPITCH;
        float acc[4] = {0.f, 0.f, 0.f, 0.f};
        #pragma unroll
        for (int kk = 0; kk < 8; kk++) {
            int k = kk * 8;
            const float* pa = qs + (warpm*16 + g)*SCQ + k + t;
            uint32_t a0 = __float_as_uint(pa[0]);
            uint32_t a1 = __float_as_uint(pa[8*SCQ]);
            uint32_t a2 = __float_as_uint(pa[4]);
            uint32_t a3 = __float_as_uint(pa[8*SCQ + 4]);
            const float* pb = ks + (warpn*8 + g)*SCK + k + t;
            uint32_t b0 = __float_as_uint(rna_tf32(pb[0]));
            uint32_t b1 = __float_as_uint(rna_tf32(pb[4]));
            mma_tf32(acc, a0, a1, a2, a3, b0, b1);
        }

        int row = warpm*16 + g;
        int col = kt*32 + warpn*8 + 2*t;
        float2 v0 = {acc[0]*SCALE, acc[1]*SCALE};
        *(float2*)&sc[row*SCS + col] = v0;
        float2 v1 = {acc[2]*SCALE, acc[3]*SCALE};
        *(float2*)&sc[(row+8)*SCS + col] = v1;
        __syncthreads();
    }

    // prefetch V stage 0 so it overlaps the softmax phase
    load_v(0, 0);
    asm volatile("cp.async.commit_group;\n" ::);

    // ---- softmax: 8 warps x 4 rows ----
    for (int r = warp*4; r < warp*4 + 4; r++) {
        float mx = -1e30f;
        for (int j = lane; j < SS; j += 32) mx = fmaxf(mx, sc[r*SCS + j]);
        #pragma unroll
        for (int o = 16; o; o >>= 1) mx = fmaxf(mx, __shfl_xor_sync(0xffffffffu, mx, o));
        float sum = 0.f;
        for (int j = lane; j < SS; j += 32) {
            float e = __expf(sc[r*SCS + j] - mx);
            sc[r*SCS + j] = e;
            sum += e;
        }
        #pragma unroll
        for (int o = 16; o; o >>= 1) sum += __shfl_xor_sync(0xffffffffu, sum, o);
        float inv = 1.f / sum;
        float* dst = attn + (((size_t)b*HH + h)*SS + s0 + r) * (size_t)SS;
        for (int j = lane; j < SS; j += 32) {
            float p = sc[r*SCS + j] * inv;
            dst[j] = p;
            sc[r*SCS + j] = rna_tf32(p);
        }
    }
    __syncthreads();

    // ---- AV: ctx = probs @ V, 18 double-buffered stages ----
    float acc[2][4];
    #pragma unroll
    for (int j = 0; j < 2; j++)
        #pragma unroll
        for (int r = 0; r < 4; r++) acc[j][r] = 0.f;

    for (int kt = 0; kt < NSTAGE; kt++) {
        int s = kt & 1;
        if (kt + 1 < NSTAGE) load_v(s ^ 1, kt + 1);
        asm volatile("cp.async.commit_group;\n" ::);
        asm volatile("cp.async.wait_group 1;\n" ::);
        __syncthreads();

        const float* vs = kv + s * KVPITCH;
        #pragma unroll
        for (int kk = 0; kk < 4; kk++) {
            int k = kk * 8;
            const float* pa = sc + (warpm*16 + g)*SCS + kt*32 + k + t;
            uint32_t a0 = __float_as_uint(pa[0]);
            uint32_t a1 = __float_as_uint(pa[8*SCS]);
            uint32_t a2 = __float_as_uint(pa[4]);
            uint32_t a3 = __float_as_uint(pa[8*SCS + 4]);
            #pragma unroll
            for (int ns = 0; ns < 2; ns++) {
                int nb = warpn*16 + ns*8;
                uint32_t b0 = __float_as_uint(rna_tf32(vs[(k + t)*VSS + nb + g]));
                uint32_t b1 = __float_as_uint(rna_tf32(vs[(k + t + 4)*VSS + nb + g]));
                mma_tf32(acc[ns], a0, a1, a2, a3, b0, b1);
            }
        }
        __syncthreads();
    }

    // ---- ctx epilogue (tf32-rounded; feeds final GEMM as A) ----
    {
        int row = warpm*16 + g;
        #pragma unroll
        for (int ns = 0; ns < 2; ns++) {
            int col = warpn*16 + ns*8 + 2*t;
            float2 v0 = {rna_tf32(acc[ns][0]), rna_tf32(acc[ns][1])};
            *(float2*)&ctx[((size_t)(b*SS + s0 + row))*DD + h*HDD + col] = v0;
            float2 v1 = {rna_tf32(acc[ns][2]), rna_tf32(acc[ns][3])};
            *(float2*)&ctx[((size_t)(b*SS + s0 + row + 8))*DD + h*HDD + col] = v1;
        }
    }
}

// ===========================================================================
extern "C" void kernel_launch(void* const* d_in, const int* in_sizes, int n_in,
                              void* d_out, int out_size)
{
    const float* x  = (const float*)d_in[0];
    const float* Wq = (const float*)d_in[1];
    const float* bq = (const float*)d_in[2];
    const float* Wk = (const float*)d_in[3];
    const float* bk = (const float*)d_in[4];
    const float* Wv = (const float*)d_in[5];
    const float* bv = (const float*)d_in[6];
    const float* Wo = (const float*)d_in[7];
    const float* bo = (const float*)d_in[8];

    float* out = (float*)d_out;
    float* attn;
    if (out_size >= OUT_ELEMS + ATTN_ELEMS) {
        attn = out + OUT_ELEMS;
    } else {
        void* p; cudaGetSymbolAddress(&p, g_attn_fallback);
        attn = (float*)p;
    }

    float *q, *k, *v, *ctx, *xr, *wq, *wk, *wv, *wo;
    { void* p; cudaGetSymbolAddress(&p, g_q);   q   = (float*)p; }
    { void* p; cudaGetSymbolAddress(&p, g_k);   k   = (float*)p; }
    { void* p; cudaGetSymbolAddress(&p, g_v);   v   = (float*)p; }
    { void* p; cudaGetSymbolAddress(&p, g_ctx); ctx = (float*)p; }
    { void* p; cudaGetSymbolAddress(&p, g_xr);  xr  = (float*)p; }
    { void* p; cudaGetSymbolAddress(&p, g_wq);  wq  = (float*)p; }
    { void* p; cudaGetSymbolAddress(&p, g_wk);  wk  = (float*)p; }
    { void* p; cudaGetSymbolAddress(&p, g_wv);  wv  = (float*)p; }
    { void* p; cudaGetSymbolAddress(&p, g_wo);  wo  = (float*)p; }

    const int gemm_smem = 4 * GS * (int)sizeof(float);
    cudaFuncSetAttribute(gemm_qkv,
                         cudaFuncAttributeMaxDynamicSharedMemorySize, gemm_smem);
    cudaFuncSetAttribute(gemm_single,
                         cudaFuncAttributeMaxDynamicSharedMemorySize, gemm_smem);
    const int attn_smem = ATTN_SMEM_FLOATS * (int)sizeof(float);  // 101376
    cudaFuncSetAttribute(attn_fused,
                         cudaFuncAttributeMaxDynamicSharedMemorySize, attn_smem);

    // 1) tf32 pre-rounding
    round_tf32_kernel<<<1184, 256>>>(x, xr, OUT_ELEMS/4);
    round_tf32_kernel<<<576, 256>>>(Wq, wq, (DD*DD)/4);
    round_tf32_kernel<<<576, 256>>>(Wk, wk, (DD*DD)/4);
    round_tf32_kernel<<<576, 256>>>(Wv, wv, (DD*DD)/4);
    round_tf32_kernel<<<576, 256>>>(Wo, wo, (DD*DD)/4);

    // 2) fused Q/K/V projections
    dim3 gQKV(DD/128, MTOK/128, 3);
    gemm_qkv<<<gQKV, 256, gemm_smem>>>(xr, wq, wk, wv, bq, bk, bv, q, k, v);

    // 3) fused scores + softmax + AV
    dim3 gAttn(SS/QROWS, HH, BB);         // (18, 12, 32)
    attn_fused<<<gAttn, 256, attn_smem>>>(q, k, v, attn, ctx);

    // 4) output projection
    dim3 gO(DD/128, MTOK/128);
    gemm_single<<<gO, 256, gemm_smem>>>(ctx, wo, bo, out);
}

// round 5
// speedup vs baseline: 1.2910x; 1.0739x over previous
#include <cuda_runtime.h>
#include <cstdint>
#include <cstddef>

#define BB 32
#define SS 576
#define DD 768
#define HH 12
#define HDD 64
#define MTOK (BB*SS)               // 18432
#define OUT_ELEMS (BB*SS*DD)       // 14155776
#define ATTN_ELEMS (BB*HH*SS*SS)   // 127401984
#define SCALE 0.125f

// ---- scratch (static device globals; no runtime allocation) ----
__device__ float g_q[OUT_ELEMS];
__device__ float g_k[OUT_ELEMS];
__device__ float g_v[OUT_ELEMS];
__device__ float g_ctx[OUT_ELEMS];
__device__ float g_xr[OUT_ELEMS];
__device__ float g_wq[DD*DD], g_wk[DD*DD], g_wv[DD*DD], g_wo[DD*DD];
__device__ float g_attn_fallback[ATTN_ELEMS];

// ---------------------------------------------------------------------------
__device__ __forceinline__ float rna_tf32(float x) {
    unsigned u;
    asm("cvt.rna.tf32.f32 %0, %1;" : "=r"(u) : "f"(x));
    return __uint_as_float(u);
}

__device__ __forceinline__ void mma_tf32(float c[4],
    uint32_t a0, uint32_t a1, uint32_t a2, uint32_t a3,
    uint32_t b0, uint32_t b1)
{
    asm volatile(
        "mma.sync.aligned.m16n8k8.row.col.f32.tf32.tf32.f32 "
        "{%0,%1,%2,%3}, {%4,%5,%6,%7}, {%8,%9}, {%0,%1,%2,%3};"
        : "+f"(c[0]), "+f"(c[1]), "+f"(c[2]), "+f"(c[3])
        : "r"(a0), "r"(a1), "r"(a2), "r"(a3), "r"(b0), "r"(b1));
}

__device__ __forceinline__ void cpa16(void* dst, const void* src) {
    uint32_t d = (uint32_t)__cvta_generic_to_shared(dst);
    asm volatile("cp.async.cg.shared.global [%0], [%1], 16;\n"
                 :: "r"(d), "l"(src));
}
#define CP_COMMIT() asm volatile("cp.async.commit_group;\n" ::)
#define CP_WAIT1()  asm volatile("cp.async.wait_group 1;\n" ::)

// ---------------------------------------------------------------------------
__global__ void round_tf32_kernel(const float* __restrict__ in,
                                  float* __restrict__ out, int n4)
{
    for (int i = blockIdx.x * blockDim.x + threadIdx.x; i < n4;
         i += gridDim.x * blockDim.x) {
        float4 v = ((const float4*)in)[i];
        v.x = rna_tf32(v.x); v.y = rna_tf32(v.y);
        v.z = rna_tf32(v.z); v.w = rna_tf32(v.w);
        ((float4*)out)[i] = v;
    }
}

// rounds the 4 weight matrices in one launch; blockIdx.y selects matrix
__global__ void round_w4_kernel(
    const float* __restrict__ w0, const float* __restrict__ w1,
    const float* __restrict__ w2, const float* __restrict__ w3,
    float* __restrict__ o0, float* __restrict__ o1,
    float* __restrict__ o2, float* __restrict__ o3, int n4)
{
    int z = blockIdx.y;
    const float* in = (z == 0) ? w0 : (z == 1) ? w1 : (z == 2) ? w2 : w3;
    float* out      = (z == 0) ? o0 : (z == 1) ? o1 : (z == 2) ? o2 : o3;
    for (int i = blockIdx.x * blockDim.x + threadIdx.x; i < n4;
         i += gridDim.x * blockDim.x) {
        float4 v = ((const float4*)in)[i];
        v.x = rna_tf32(v.x); v.y = rna_tf32(v.y);
        v.z = rna_tf32(v.z); v.w = rna_tf32(v.w);
        ((float4*)out)[i] = v;
    }
}

// ---------------------------------------------------------------------------
// GEMM: C[M,N] = A[M,K] @ W^T + bias.  A,W pre-rounded to tf32.
// BM=128, BN=128, BK=32, 256 threads, tf32 mma.
// 3-stage cp.async pipeline, one __syncthreads per iteration.
// smem: 3 stages x (A 128x36 + B 128x36) = 110592 B.
// ---------------------------------------------------------------------------
#define GST (2*128*36)   // floats per stage (A+B)

__device__ __forceinline__ void gemm_body(
    const float* __restrict__ A, const float* __restrict__ W,
    const float* __restrict__ bias, float* __restrict__ C,
    int N, int K)
{
    extern __shared__ float dsm[];

    const int tid = threadIdx.x;
    const int m0 = blockIdx.y * 128;
    const int n0 = blockIdx.x * 128;
    const int warp = tid >> 5;
    const int lane = tid & 31;
    const int g = lane >> 2;
    const int t = lane & 3;
    const int warpm = warp >> 2;
    const int warpn = warp & 3;

    float acc[4][4][4];
    #pragma unroll
    for (int i = 0; i < 4; i++)
        #pragma unroll
        for (int j = 0; j < 4; j++)
            #pragma unroll
            for (int r = 0; r < 4; r++) acc[i][j][r] = 0.f;

    auto load_stage = [&](int st, int k0) {
        float* as = dsm + st * GST;
        float* bs = as + 128*36;
        #pragma unroll
        for (int i = 0; i < 4; i++) {
            int c = tid + i * 256;
            int row = c >> 3, seg = c & 7;
            cpa16(&as[row*36 + seg*4], &A[(size_t)(m0 + row) * K + k0 + seg*4]);
        }
        #pragma unroll
        for (int i = 0; i < 4; i++) {
            int c = tid + i * 256;
            int row = c >> 3, seg = c & 7;
            cpa16(&bs[row*36 + seg*4], &W[(size_t)(n0 + row) * K + k0 + seg*4]);
        }
    };

    const int iters = K / 32;            // 24
    load_stage(0, 0);  CP_COMMIT();
    load_stage(1, 32); CP_COMMIT();

    for (int it = 0; it < iters; ++it) {
        CP_WAIT1();
        __syncthreads();
        if (it + 2 < iters) load_stage((it + 2) % 3, (it + 2) * 32);
        CP_COMMIT();

        const float* as = dsm + (it % 3) * GST;
        const float* bs = as + 128*36;
        #pragma unroll
        for (int ks = 0; ks < 4; ks++) {
            int k = ks * 8;
            uint32_t af[4][4];
            #pragma unroll
            for (int ms = 0; ms < 4; ms++) {
                const float* p = as + (warpm*64 + ms*16 + g) * 36 + k + t;
                af[ms][0] = __float_as_uint(p[0]);
                af[ms][1] = __float_as_uint(p[8*36]);
                af[ms][2] = __float_as_uint(p[4]);
                af[ms][3] = __float_as_uint(p[8*36 + 4]);
            }
            #pragma unroll
            for (int ns = 0; ns < 4; ns++) {
                const float* p = bs + (warpn*32 + ns*8 + g) * 36 + k + t;
                uint32_t b0 = __float_as_uint(p[0]);
                uint32_t b1 = __float_as_uint(p[4]);
                #pragma unroll
                for (int ms = 0; ms < 4; ms++)
                    mma_tf32(acc[ms][ns], af[ms][0], af[ms][1], af[ms][2],
                             af[ms][3], b0, b1);
            }
        }
    }

    #pragma unroll
    for (int ms = 0; ms < 4; ms++) {
        int row0 = m0 + warpm*64 + ms*16 + g;
        #pragma unroll
        for (int ns = 0; ns < 4; ns++) {
            int col = n0 + warpn*32 + ns*8 + 2*t;
            float b0v = bias[col], b1v = bias[col + 1];
            float2 v0 = {acc[ms][ns][0] + b0v, acc[ms][ns][1] + b1v};
            *(float2*)&C[(size_t)row0 * N + col] = v0;
            float2 v1 = {acc[ms][ns][2] + b0v, acc[ms][ns][3] + b1v};
            *(float2*)&C[(size_t)(row0 + 8) * N + col] = v1;
        }
    }
}

__global__ __launch_bounds__(256) void gemm_qkv(
    const float* __restrict__ A,
    const float* __restrict__ Wq, const float* __restrict__ Wk,
    const float* __restrict__ Wv,
    const float* __restrict__ bq, const float* __restrict__ bk,
    const float* __restrict__ bv,
    float* __restrict__ Cq, float* __restrict__ Ck, float* __restrict__ Cv)
{
    int z = blockIdx.z;
    const float* W    = (z == 0) ? Wq : (z == 1) ? Wk : Wv;
    const float* bias = (z == 0) ? bq : (z == 1) ? bk : bv;
    float*       C    = (z == 0) ? Cq : (z == 1) ? Ck : Cv;
    gemm_body(A, W, bias, C, DD, DD);
}

__global__ __launch_bounds__(256) void gemm_single(
    const float* __restrict__ A, const float* __restrict__ W,
    const float* __restrict__ bias, float* __restrict__ C)
{
    gemm_body(A, W, bias, C, DD, DD);
}

// ---------------------------------------------------------------------------
// Fused attention per (b, h, 32-query tile).
// Q fragments hoisted to registers (loop-invariant across key stages).
// 3-stage cp.async KV pipeline, one __syncthreads per stage.
// smem: qs[32][68] + kv[3][32*72] + sc[32][580] = 110592 B -> 2 CTA/SM.
// ---------------------------------------------------------------------------
#define SCQ 68
#define SCK 68
#define VSS 72
#define KVPITCH (32*72)
#define SCS 580
#define QROWS 32
#define NSTAGE (SS/32)  // 18
#define ATTN_SMEM_FLOATS (QROWS*SCQ + 3*KVPITCH + QROWS*SCS)  // 27648

__global__ __launch_bounds__(256) void attn_fused(
    const float* __restrict__ Q, const float* __restrict__ K,
    const float* __restrict__ V, float* __restrict__ attn,
    float* __restrict__ ctx)
{
    extern __shared__ float smem[];
    float* qs = smem;                         // [32][SCQ]
    float* kv = smem + QROWS*SCQ;             // 3 stage buffers
    float* sc = smem + QROWS*SCQ + 3*KVPITCH; // [32][SCS]

    const int qt = blockIdx.x, h = blockIdx.y, b = blockIdx.z;
    const int s0 = qt * QROWS;
    const int tid = threadIdx.x;
    const int warp = tid >> 5;
    const int lane = tid & 31;
    const int g = lane >> 2, t = lane & 3;
    const int warpm = warp >> 2;   // 0..1
    const int warpn = warp & 3;    // 0..3

    const size_t kvbase = (size_t)b * SS * DD + h * HDD;

    // ---- load Q tile (rna to tf32) ----
    #pragma unroll
    for (int i = 0; i < 2; i++) {
        int c = tid + i * 256;
        int qi = c >> 4, d4 = c & 15;
        float4 v = *(const float4*)&Q[((size_t)(b*SS + s0 + qi))*DD + h*HDD + d4*4];
        float* p = qs + qi*SCQ + d4*4;
        p[0] = rna_tf32(v.x); p[1] = rna_tf32(v.y);
        p[2] = rna_tf32(v.z); p[3] = rna_tf32(v.w);
    }

    auto load_k = [&](int st, int kt) {
        float* dst = kv + st * KVPITCH;
        #pragma unroll
        for (int i = 0; i < 2; i++) {
            int c = tid + i * 256;
            int row = c >> 4, seg = c & 15;
            cpa16(&dst[row*SCK + seg*4],
                  &K[kvbase + (size_t)(kt*32 + row)*DD + seg*4]);
        }
    };
    auto load_v = [&](int st, int kt) {
        float* dst = kv + st * KVPITCH;
        #pragma unroll
        for (int i = 0; i < 2; i++) {
            int c = tid + i * 256;
            int row = c >> 4, seg = c & 15;
            cpa16(&dst[row*VSS + seg*4],
                  &V[kvbase + (size_t)(kt*32 + row)*DD + seg*4]);
        }
    };

    load_k(0, 0); CP_COMMIT();
    load_k(1, 1); CP_COMMIT();
    __syncthreads();   // qs visible to all warps

    // ---- hoist Q fragments into registers (invariant over key stages) ----
    uint32_t qa[8][4];
    #pragma unroll
    for (int kk = 0; kk < 8; kk++) {
        const float* pa = qs + (warpm*16 + g)*SCQ + kk*8 + t;
        qa[kk][0] = __float_as_uint(pa[0]);
        qa[kk][1] = __float_as_uint(pa[8*SCQ]);
        qa[kk][2] = __float_as_uint(pa[4]);
        qa[kk][3] = __float_as_uint(pa[8*SCQ + 4]);
    }

    // ---- scores: QK^T into sc strip, 18 pipelined stages ----
    for (int kt = 0; kt < NSTAGE; kt++) {
        CP_WAIT1();
        __syncthreads();
        if (kt + 2 < NSTAGE) load_k((kt + 2) % 3, kt + 2);
        CP_COMMIT();

        const float* ks = kv + (kt % 3) * KVPITCH;
        float acc[4] = {0.f, 0.f, 0.f, 0.f};
        #pragma unroll
        for (int kk = 0; kk < 8; kk++) {
            const float* pb = ks + (warpn*8 + g)*SCK + kk*8 + t;
            uint32_t b0 = __float_as_uint(rna_tf32(pb[0]));
            uint32_t b1 = __float_as_uint(rna_tf32(pb[4]));
            mma_tf32(acc, qa[kk][0], qa[kk][1], qa[kk][2], qa[kk][3], b0, b1);
        }

        int row = warpm*16 + g;
        int col = kt*32 + warpn*8 + 2*t;
        float2 v0 = {acc[0]*SCALE, acc[1]*SCALE};
        *(float2*)&sc[row*SCS + col] = v0;
        float2 v1 = {acc[2]*SCALE, acc[3]*SCALE};
        *(float2*)&sc[(row+8)*SCS + col] = v1;
    }
    __syncthreads();   // all scores written (also: all stage-17 reads done)

    // prefetch V stages 0,1 (slots 0,1 are no longer read) -> overlaps softmax
    load_v(0, 0); CP_COMMIT();
    load_v(1, 1); CP_COMMIT();

    // ---- softmax: 8 warps x 4 rows ----
    for (int r = warp*4; r < warp*4 + 4; r++) {
        float mx = -1e30f;
        for (int j = lane; j < SS; j += 32) mx = fmaxf(mx, sc[r*SCS + j]);
        #pragma unroll
        for (int o = 16; o; o >>= 1) mx = fmaxf(mx, __shfl_xor_sync(0xffffffffu, mx, o));
        float sum = 0.f;
        for (int j = lane; j < SS; j += 32) {
            float e = __expf(sc[r*SCS + j] - mx);
            sc[r*SCS + j] = e;
            sum += e;
        }
        #pragma unroll
        for (int o = 16; o; o >>= 1) sum += __shfl_xor_sync(0xffffffffu, sum, o);
        float inv = 1.f / sum;
        float* dst = attn + (((size_t)b*HH + h)*SS + s0 + r) * (size_t)SS;
        for (int j = lane; j < SS; j += 32) {
            float p = sc[r*SCS + j] * inv;
            dst[j] = p;
            sc[r*SCS + j] = rna_tf32(p);
        }
    }
    __syncthreads();

    // ---- AV: ctx = probs @ V, 18 pipelined stages ----
    float acc[2][4];
    #pragma unroll
    for (int j = 0; j < 2; j++)
        #pragma unroll
        for (int r = 0; r < 4; r++) acc[j][r] = 0.f;

    for (int kt = 0; kt < NSTAGE; kt++) {
        CP_WAIT1();
        __syncthreads();
        if (kt + 2 < NSTAGE) load_v((kt + 2) % 3, kt + 2);
        CP_COMMIT();

        const float* vs = kv + (kt % 3) * KVPITCH;
        #pragma unroll
        for (int kk = 0; kk < 4; kk++) {
            int k = kk * 8;
            const float* pa = sc + (warpm*16 + g)*SCS + kt*32 + k + t;
            uint32_t a0 = __float_as_uint(pa[0]);
            uint32_t a1 = __float_as_uint(pa[8*SCS]);
            uint32_t a2 = __float_as_uint(pa[4]);
            uint32_t a3 = __float_as_uint(pa[8*SCS + 4]);
            #pragma unroll
            for (int ns = 0; ns < 2; ns++) {
                int nb = warpn*16 + ns*8;
                uint32_t b0 = __float_as_uint(rna_tf32(vs[(k + t)*VSS + nb + g]));
                uint32_t b1 = __float_as_uint(rna_tf32(vs[(k + t + 4)*VSS + nb + g]));
                mma_tf32(acc[ns], a0, a1, a2, a3, b0, b1);
            }
        }
    }

    // ---- ctx epilogue (tf32-rounded; feeds final GEMM as A) ----
    {
        int row = warpm*16 + g;
        #pragma unroll
        for (int ns = 0; ns < 2; ns++) {
            int col = warpn*16 + ns*8 + 2*t;
            float2 v0 = {rna_tf32(acc[ns][0]), rna_tf32(acc[ns][1])};
            *(float2*)&ctx[((size_t)(b*SS + s0 + row))*DD + h*HDD + col] = v0;
            float2 v1 = {rna_tf32(acc[ns][2]), rna_tf32(acc[ns][3])};
            *(float2*)&ctx[((size_t)(b*SS + s0 + row + 8))*DD + h*HDD + col] = v1;
        }
    }
}

// ===========================================================================
extern "C" void kernel_launch(void* const* d_in, const int* in_sizes, int n_in,
                              void* d_out, int out_size)
{
    const float* x  = (const float*)d_in[0];
    const float* Wq = (const float*)d_in[1];
    const float* bq = (const float*)d_in[2];
    const float* Wk = (const float*)d_in[3];
    const float* bk = (const float*)d_in[4];
    const float* Wv = (const float*)d_in[5];
    const float* bv = (const float*)d_in[6];
    const float* Wo = (const float*)d_in[7];
    const float* bo = (const float*)d_in[8];

    float* out = (float*)d_out;
    float* attn;
    if (out_size >= OUT_ELEMS + ATTN_ELEMS) {
        attn = out + OUT_ELEMS;
    } else {
        void* p; cudaGetSymbolAddress(&p, g_attn_fallback);
        attn = (float*)p;
    }

    float *q, *k, *v, *ctx, *xr, *wq, *wk, *wv, *wo;
    { void* p; cudaGetSymbolAddress(&p, g_q);   q   = (float*)p; }
    { void* p; cudaGetSymbolAddress(&p, g_k);   k   = (float*)p; }
    { void* p; cudaGetSymbolAddress(&p, g_v);   v   = (float*)p; }
    { void* p; cudaGetSymbolAddress(&p, g_ctx); ctx = (float*)p; }
    { void* p; cudaGetSymbolAddress(&p, g_xr);  xr  = (float*)p; }
    { void* p; cudaGetSymbolAddress(&p, g_wq);  wq  = (float*)p; }
    { void* p; cudaGetSymbolAddress(&p, g_wk);  wk  = (float*)p; }
    { void* p; cudaGetSymbolAddress(&p, g_wv);  wv  = (float*)p; }
    { void* p; cudaGetSymbolAddress(&p, g_wo);  wo  = (float*)p; }

    const int gemm_smem = 3 * GST * (int)sizeof(float);          // 110592
    cudaFuncSetAttribute(gemm_qkv,
                         cudaFuncAttributeMaxDynamicSharedMemorySize, gemm_smem);
    cudaFuncSetAttribute(gemm_single,
                         cudaFuncAttributeMaxDynamicSharedMemorySize, gemm_smem);
    const int attn_smem = ATTN_SMEM_FLOATS * (int)sizeof(float); // 110592
    cudaFuncSetAttribute(attn_fused,
                         cudaFuncAttributeMaxDynamicSharedMemorySize, attn_smem);

    // 1) tf32 pre-rounding
    round_tf32_kernel<<<1184, 256>>>(x, xr, OUT_ELEMS/4);
    dim3 gW(288, 4);
    round_w4_kernel<<<gW, 256>>>(Wq, Wk, Wv, Wo, wq, wk, wv, wo, (DD*DD)/4);

    // 2) fused Q/K/V projections
    dim3 gQKV(DD/128, MTOK/128, 3);
    gemm_qkv<<<gQKV, 256, gemm_smem>>>(xr, wq, wk, wv, bq, bk, bv, q, k, v);

    // 3) fused scores + softmax + AV
    dim3 gAttn(SS/QROWS, HH, BB);         // (18, 12, 32)
    attn_fused<<<gAttn, 256, attn_smem>>>(q, k, v, attn, ctx);

    // 4) output projection
    dim3 gO(DD/128, MTOK/128);
    gemm_single<<<gO, 256, gemm_smem>>>(ctx, wo, bo, out);
}

// round 6
// speedup vs baseline: 1.3151x; 1.0186x over previous
#include <cuda_runtime.h>
#include <cstdint>
#include <cstddef>

#define BB 32
#define SS 576
#define DD 768
#define HH 12
#define HDD 64
#define MTOK (BB*SS)               // 18432
#define OUT_ELEMS (BB*SS*DD)       // 14155776
#define ATTN_ELEMS (BB*HH*SS*SS)   // 127401984
#define SCALE 0.125f

// ---- scratch (static device globals; no runtime allocation) ----
__device__ float g_q[OUT_ELEMS];
__device__ float g_k[OUT_ELEMS];
__device__ float g_v[OUT_ELEMS];
__device__ float g_ctx[OUT_ELEMS];
__device__ float g_xr[OUT_ELEMS];
__device__ float g_wq[DD*DD], g_wk[DD*DD], g_wv[DD*DD], g_wo[DD*DD];
__device__ float g_attn_fallback[ATTN_ELEMS];

// ---------------------------------------------------------------------------
__device__ __forceinline__ float rna_tf32(float x) {
    unsigned u;
    asm("cvt.rna.tf32.f32 %0, %1;" : "=r"(u) : "f"(x));
    return __uint_as_float(u);
}

__device__ __forceinline__ void mma_tf32(float c[4],
    uint32_t a0, uint32_t a1, uint32_t a2, uint32_t a3,
    uint32_t b0, uint32_t b1)
{
    asm volatile(
        "mma.sync.aligned.m16n8k8.row.col.f32.tf32.tf32.f32 "
        "{%0,%1,%2,%3}, {%4,%5,%6,%7}, {%8,%9}, {%0,%1,%2,%3};"
        : "+f"(c[0]), "+f"(c[1]), "+f"(c[2]), "+f"(c[3])
        : "r"(a0), "r"(a1), "r"(a2), "r"(a3), "r"(b0), "r"(b1));
}

__device__ __forceinline__ void cpa16(void* dst, const void* src) {
    uint32_t d = (uint32_t)__cvta_generic_to_shared(dst);
    asm volatile("cp.async.cg.shared.global [%0], [%1], 16;\n"
                 :: "r"(d), "l"(src));
}
#define CP_COMMIT() asm volatile("cp.async.commit_group;\n" ::)
#define CP_WAIT1()  asm volatile("cp.async.wait_group 1;\n" ::)
#define CP_WAIT2()  asm volatile("cp.async.wait_group 2;\n" ::)

// ---------------------------------------------------------------------------
__global__ void round_tf32_kernel(const float* __restrict__ in,
                                  float* __restrict__ out, int n4)
{
    for (int i = blockIdx.x * blockDim.x + threadIdx.x; i < n4;
         i += gridDim.x * blockDim.x) {
        float4 v = ((const float4*)in)[i];
        v.x = rna_tf32(v.x); v.y = rna_tf32(v.y);
        v.z = rna_tf32(v.z); v.w = rna_tf32(v.w);
        ((float4*)out)[i] = v;
    }
}

__global__ void round_w4_kernel(
    const float* __restrict__ w0, const float* __restrict__ w1,
    const float* __restrict__ w2, const float* __restrict__ w3,
    float* __restrict__ o0, float* __restrict__ o1,
    float* __restrict__ o2, float* __restrict__ o3, int n4)
{
    int z = blockIdx.y;
    const float* in = (z == 0) ? w0 : (z == 1) ? w1 : (z == 2) ? w2 : w3;
    float* out      = (z == 0) ? o0 : (z == 1) ? o1 : (z == 2) ? o2 : o3;
    for (int i = blockIdx.x * blockDim.x + threadIdx.x; i < n4;
         i += gridDim.x * blockDim.x) {
        float4 v = ((const float4*)in)[i];
        v.x = rna_tf32(v.x); v.y = rna_tf32(v.y);
        v.z = rna_tf32(v.z); v.w = rna_tf32(v.w);
        ((float4*)out)[i] = v;
    }
}

// ---------------------------------------------------------------------------
// GEMM: C[M,N] = A[M,K] @ W^T + bias.  A,W pre-rounded to tf32.
// RND: round output to tf32 at store (for Q/K/V feeding attention mma).
// BM=128, BN=128, BK=32, 256 threads, 3-stage cp.async pipeline.
// ---------------------------------------------------------------------------
#define GST (2*128*36)   // floats per stage (A+B)

template <bool RND>
__device__ __forceinline__ void gemm_body(
    const float* __restrict__ A, const float* __restrict__ W,
    const float* __restrict__ bias, float* __restrict__ C,
    int N, int K)
{
    extern __shared__ float dsm[];

    const int tid = threadIdx.x;
    const int m0 = blockIdx.y * 128;
    const int n0 = blockIdx.x * 128;
    const int warp = tid >> 5;
    const int lane = tid & 31;
    const int g = lane >> 2;
    const int t = lane & 3;
    const int warpm = warp >> 2;
    const int warpn = warp & 3;

    float acc[4][4][4];
    #pragma unroll
    for (int i = 0; i < 4; i++)
        #pragma unroll
        for (int j = 0; j < 4; j++)
            #pragma unroll
            for (int r = 0; r < 4; r++) acc[i][j][r] = 0.f;

    auto load_stage = [&](int st, int k0) {
        float* as = dsm + st * GST;
        float* bs = as + 128*36;
        #pragma unroll
        for (int i = 0; i < 4; i++) {
            int c = tid + i * 256;
            int row = c >> 3, seg = c & 7;
            cpa16(&as[row*36 + seg*4], &A[(size_t)(m0 + row) * K + k0 + seg*4]);
        }
        #pragma unroll
        for (int i = 0; i < 4; i++) {
            int c = tid + i * 256;
            int row = c >> 3, seg = c & 7;
            cpa16(&bs[row*36 + seg*4], &W[(size_t)(n0 + row) * K + k0 + seg*4]);
        }
    };

    const int iters = K / 32;            // 24
    load_stage(0, 0);  CP_COMMIT();
    load_stage(1, 32); CP_COMMIT();

    for (int it = 0; it < iters; ++it) {
        CP_WAIT1();
        __syncthreads();
        if (it + 2 < iters) load_stage((it + 2) % 3, (it + 2) * 32);
        CP_COMMIT();

        const float* as = dsm + (it % 3) * GST;
        const float* bs = as + 128*36;
        #pragma unroll
        for (int ks = 0; ks < 4; ks++) {
            int k = ks * 8;
            uint32_t af[4][4];
            #pragma unroll
            for (int ms = 0; ms < 4; ms++) {
                const float* p = as + (warpm*64 + ms*16 + g) * 36 + k + t;
                af[ms][0] = __float_as_uint(p[0]);
                af[ms][1] = __float_as_uint(p[8*36]);
                af[ms][2] = __float_as_uint(p[4]);
                af[ms][3] = __float_as_uint(p[8*36 + 4]);
            }
            #pragma unroll
            for (int ns = 0; ns < 4; ns++) {
                const float* p = bs + (warpn*32 + ns*8 + g) * 36 + k + t;
                uint32_t b0 = __float_as_uint(p[0]);
                uint32_t b1 = __float_as_uint(p[4]);
                #pragma unroll
                for (int ms = 0; ms < 4; ms++)
                    mma_tf32(acc[ms][ns], af[ms][0], af[ms][1], af[ms][2],
                             af[ms][3], b0, b1);
            }
        }
    }

    #pragma unroll
    for (int ms = 0; ms < 4; ms++) {
        int row0 = m0 + warpm*64 + ms*16 + g;
        #pragma unroll
        for (int ns = 0; ns < 4; ns++) {
            int col = n0 + warpn*32 + ns*8 + 2*t;
            float b0v = bias[col], b1v = bias[col + 1];
            float2 v0, v1;
            if (RND) {
                v0 = {rna_tf32(acc[ms][ns][0] + b0v), rna_tf32(acc[ms][ns][1] + b1v)};
                v1 = {rna_tf32(acc[ms][ns][2] + b0v), rna_tf32(acc[ms][ns][3] + b1v)};
            } else {
                v0 = {acc[ms][ns][0] + b0v, acc[ms][ns][1] + b1v};
                v1 = {acc[ms][ns][2] + b0v, acc[ms][ns][3] + b1v};
            }
            *(float2*)&C[(size_t)row0 * N + col] = v0;
            *(float2*)&C[(size_t)(row0 + 8) * N + col] = v1;
        }
    }
}

__global__ __launch_bounds__(256) void gemm_qkv(
    const float* __restrict__ A,
    const float* __restrict__ Wq, const float* __restrict__ Wk,
    const float* __restrict__ Wv,
    const float* __restrict__ bq, const float* __restrict__ bk,
    const float* __restrict__ bv,
    float* __restrict__ Cq, float* __restrict__ Ck, float* __restrict__ Cv)
{
    int z = blockIdx.z;
    const float* W    = (z == 0) ? Wq : (z == 1) ? Wk : Wv;
    const float* bias = (z == 0) ? bq : (z == 1) ? bk : bv;
    float*       C    = (z == 0) ? Cq : (z == 1) ? Ck : Cv;
    gemm_body<true>(A, W, bias, C, DD, DD);   // rna-rounded Q/K/V
}

__global__ __launch_bounds__(256) void gemm_single(
    const float* __restrict__ A, const float* __restrict__ W,
    const float* __restrict__ bias, float* __restrict__ C)
{
    gemm_body<false>(A, W, bias, C, DD, DD);
}

// ---------------------------------------------------------------------------
// Fused attention per (b, h, 32-query tile).
// Q/K/V arrive pre-rounded to tf32 -> NO cvt in the hot loops.
// Q tile via cp.async; Q fragments hoisted to registers.
// 3-stage cp.async KV pipeline, one __syncthreads per stage.
// smem: qs[32][68] + kv[3][32*72] + sc[32][580] = 110592 B -> 2 CTA/SM.
// ---------------------------------------------------------------------------
#define SCQ 68
#define SCK 68
#define VSS 72
#define KVPITCH (32*72)
#define SCS 580
#define QROWS 32
#define NSTAGE (SS/32)  // 18
#define ATTN_SMEM_FLOATS (QROWS*SCQ + 3*KVPITCH + QROWS*SCS)  // 27648

__global__ __launch_bounds__(256) void attn_fused(
    const float* __restrict__ Q, const float* __restrict__ K,
    const float* __restrict__ V, float* __restrict__ attn,
    float* __restrict__ ctx)
{
    extern __shared__ float smem[];
    float* qs = smem;                         // [32][SCQ]
    float* kv = smem + QROWS*SCQ;             // 3 stage buffers
    float* sc = smem + QROWS*SCQ + 3*KVPITCH; // [32][SCS]

    const int qt = blockIdx.x, h = blockIdx.y, b = blockIdx.z;
    const int s0 = qt * QROWS;
    const int tid = threadIdx.x;
    const int warp = tid >> 5;
    const int lane = tid & 31;
    const int g = lane >> 2, t = lane & 3;
    const int warpm = warp >> 2;   // 0..1
    const int warpn = warp & 3;    // 0..3

    const size_t kvbase = (size_t)b * SS * DD + h * HDD;

    auto load_q = [&]() {
        #pragma unroll
        for (int i = 0; i < 2; i++) {
            int c = tid + i * 256;
            int qi = c >> 4, seg = c & 15;
            cpa16(&qs[qi*SCQ + seg*4],
                  &Q[kvbase + (size_t)(s0 + qi)*DD + seg*4]);
        }
    };
    auto load_k = [&](int st, int kt) {
        float* dst = kv + st * KVPITCH;
        #pragma unroll
        for (int i = 0; i < 2; i++) {
            int c = tid + i * 256;
            int row = c >> 4, seg = c & 15;
            cpa16(&dst[row*SCK + seg*4],
                  &K[kvbase + (size_t)(kt*32 + row)*DD + seg*4]);
        }
    };
    auto load_v = [&](int st, int kt) {
        float* dst = kv + st * KVPITCH;
        #pragma unroll
        for (int i = 0; i < 2; i++) {
            int c = tid + i * 256;
            int row = c >> 4, seg = c & 15;
            cpa16(&dst[row*VSS + seg*4],
                  &V[kvbase + (size_t)(kt*32 + row)*DD + seg*4]);
        }
    };

    load_q();     CP_COMMIT();
    load_k(0, 0); CP_COMMIT();
    load_k(1, 1); CP_COMMIT();

    // wait for Q group, then hoist Q fragments into registers
    CP_WAIT2();
    __syncthreads();
    uint32_t qa[8][4];
    #pragma unroll
    for (int kk = 0; kk < 8; kk++) {
        const float* pa = qs + (warpm*16 + g)*SCQ + kk*8 + t;
        qa[kk][0] = __float_as_uint(pa[0]);
        qa[kk][1] = __float_as_uint(pa[8*SCQ]);
        qa[kk][2] = __float_as_uint(pa[4]);
        qa[kk][3] = __float_as_uint(pa[8*SCQ + 4]);
    }

    // ---- scores: QK^T into sc strip, 18 pipelined stages ----
    for (int kt = 0; kt < NSTAGE; kt++) {
        CP_WAIT1();
        __syncthreads();
        if (kt + 2 < NSTAGE) load_k((kt + 2) % 3, kt + 2);
        CP_COMMIT();

        const float* ks = kv + (kt % 3) * KVPITCH;
        float acc[4] = {0.f, 0.f, 0.f, 0.f};
        #pragma unroll
        for (int kk = 0; kk < 8; kk++) {
            const float* pb = ks + (warpn*8 + g)*SCK + kk*8 + t;
            uint32_t b0 = __float_as_uint(pb[0]);
            uint32_t b1 = __float_as_uint(pb[4]);
            mma_tf32(acc, qa[kk][0], qa[kk][1], qa[kk][2], qa[kk][3], b0, b1);
        }

        int row = warpm*16 + g;
        int col = kt*32 + warpn*8 + 2*t;
        float2 v0 = {acc[0]*SCALE, acc[1]*SCALE};
        *(float2*)&sc[row*SCS + col] = v0;
        float2 v1 = {acc[2]*SCALE, acc[3]*SCALE};
        *(float2*)&sc[(row+8)*SCS + col] = v1;
    }
    __syncthreads();

    // prefetch V stages 0,1 -> overlaps softmax
    load_v(0, 0); CP_COMMIT();
    load_v(1, 1); CP_COMMIT();

    // ---- softmax: 8 warps x 4 rows ----
    for (int r = warp*4; r < warp*4 + 4; r++) {
        float mx = -1e30f;
        for (int j = lane; j < SS; j += 32) mx = fmaxf(mx, sc[r*SCS + j]);
        #pragma unroll
        for (int o = 16; o; o >>= 1) mx = fmaxf(mx, __shfl_xor_sync(0xffffffffu, mx, o));
        float sum = 0.f;
        for (int j = lane; j < SS; j += 32) {
            float e = __expf(sc[r*SCS + j] - mx);
            sc[r*SCS + j] = e;
            sum += e;
        }
        #pragma unroll
        for (int o = 16; o; o >>= 1) sum += __shfl_xor_sync(0xffffffffu, sum, o);
        float inv = 1.f / sum;
        float* dst = attn + (((size_t)b*HH + h)*SS + s0 + r) * (size_t)SS;
        for (int j = lane; j < SS; j += 32) {
            float p = sc[r*SCS + j] * inv;
            dst[j] = p;                       // full-precision attn output
            sc[r*SCS + j] = rna_tf32(p);      // tf32 for AV mma
        }
    }
    __syncthreads();

    // ---- AV: ctx = probs @ V, 18 pipelined stages ----
    float acc[2][4];
    #pragma unroll
    for (int j = 0; j < 2; j++)
        #pragma unroll
        for (int r = 0; r < 4; r++) acc[j][r] = 0.f;

    for (int kt = 0; kt < NSTAGE; kt++) {
        CP_WAIT1();
        __syncthreads();
        if (kt + 2 < NSTAGE) load_v((kt + 2) % 3, kt + 2);
        CP_COMMIT();

        const float* vs = kv + (kt % 3) * KVPITCH;
        #pragma unroll
        for (int kk = 0; kk < 4; kk++) {
            int k = kk * 8;
            const float* pa = sc + (warpm*16 + g)*SCS + kt*32 + k + t;
            uint32_t a0 = __float_as_uint(pa[0]);
            uint32_t a1 = __float_as_uint(pa[8*SCS]);
            uint32_t a2 = __float_as_uint(pa[4]);
            uint32_t a3 = __float_as_uint(pa[8*SCS + 4]);
            #pragma unroll
            for (int ns = 0; ns < 2; ns++) {
                int nb = warpn*16 + ns*8;
                uint32_t b0 = __float_as_uint(vs[(k + t)*VSS + nb + g]);
                uint32_t b1 = __float_as_uint(vs[(k + t + 4)*VSS + nb + g]);
                mma_tf32(acc[ns], a0, a1, a2, a3, b0, b1);
            }
        }
    }

    // ---- ctx epilogue (tf32-rounded; feeds final GEMM as A) ----
    {
        int row = warpm*16 + g;
        #pragma unroll
        for (int ns = 0; ns < 2; ns++) {
            int col = warpn*16 + ns*8 + 2*t;
            float2 v0 = {rna_tf32(acc[ns][0]), rna_tf32(acc[ns][1])};
            *(float2*)&ctx[((size_t)(b*SS + s0 + row))*DD + h*HDD + col] = v0;
            float2 v1 = {rna_tf32(acc[ns][2]), rna_tf32(acc[ns][3])};
            *(float2*)&ctx[((size_t)(b*SS + s0 + row + 8))*DD + h*HDD + col] = v1;
        }
    }
}

// ===========================================================================
extern "C" void kernel_launch(void* const* d_in, const int* in_sizes, int n_in,
                              void* d_out, int out_size)
{
    const float* x  = (const float*)d_in[0];
    const float* Wq = (const float*)d_in[1];
    const float* bq = (const float*)d_in[2];
    const float* Wk = (const float*)d_in[3];
    const float* bk = (const float*)d_in[4];
    const float* Wv = (const float*)d_in[5];
    const float* bv = (const float*)d_in[6];
    const float* Wo = (const float*)d_in[7];
    const float* bo = (const float*)d_in[8];

    float* out = (float*)d_out;
    float* attn;
    if (out_size >= OUT_ELEMS + ATTN_ELEMS) {
        attn = out + OUT_ELEMS;
    } else {
        void* p; cudaGetSymbolAddress(&p, g_attn_fallback);
        attn = (float*)p;
    }

    float *q, *k, *v, *ctx, *xr, *wq, *wk, *wv, *wo;
    { void* p; cudaGetSymbolAddress(&p, g_q);   q   = (float*)p; }
    { void* p; cudaGetSymbolAddress(&p, g_k);   k   = (float*)p; }
    { void* p; cudaGetSymbolAddress(&p, g_v);   v   = (float*)p; }
    { void* p; cudaGetSymbolAddress(&p, g_ctx); ctx = (float*)p; }
    { void* p; cudaGetSymbolAddress(&p, g_xr);  xr  = (float*)p; }
    { void* p; cudaGetSymbolAddress(&p, g_wq);  wq  = (float*)p; }
    { void* p; cudaGetSymbolAddress(&p, g_wk);  wk  = (float*)p; }
    { void* p; cudaGetSymbolAddress(&p, g_wv);  wv  = (float*)p; }
    { void* p; cudaGetSymbolAddress(&p, g_wo);  wo  = (float*)p; }

    const int gemm_smem = 3 * GST * (int)sizeof(float);          // 110592
    cudaFuncSetAttribute(gemm_qkv,
                         cudaFuncAttributeMaxDynamicSharedMemorySize, gemm_smem);
    cudaFuncSetAttribute(gemm_single,
                         cudaFuncAttributeMaxDynamicSharedMemorySize, gemm_smem);
    const int attn_smem = ATTN_SMEM_FLOATS * (int)sizeof(float); // 110592
    cudaFuncSetAttribute(attn_fused,
                         cudaFuncAttributeMaxDynamicSharedMemorySize, attn_smem);

    // 1) tf32 pre-rounding
    round_tf32_kernel<<<1184, 256>>>(x, xr, OUT_ELEMS/4);
    dim3 gW(288, 4);
    round_w4_kernel<<<gW, 256>>>(Wq, Wk, Wv, Wo, wq, wk, wv, wo, (DD*DD)/4);

    // 2) fused Q/K/V projections (outputs rna-rounded to tf32)
    dim3 gQKV(DD/128, MTOK/128, 3);
    gemm_qkv<<<gQKV, 256, gemm_smem>>>(xr, wq, wk, wv, bq, bk, bv, q, k, v);

    // 3) fused scores + softmax + AV
    dim3 gAttn(SS/QROWS, HH, BB);         // (18, 12, 32)
    attn_fused<<<gAttn, 256, attn_smem>>>(q, k, v, attn, ctx);

    // 4) output projection
    dim3 gO(DD/128, MTOK/128);
    gemm_single<<<gO, 256, gemm_smem>>>(ctx, wo, bo, out);
}

// round 7
// speedup vs baseline: 1.4201x; 1.0799x over previous
#include <cuda_runtime.h>
#include <cstdint>
#include <cstddef>

#define BB 32
#define SS 576
#define DD 768
#define HH 12
#define HDD 64
#define MTOK (BB*SS)               // 18432
#define OUT_ELEMS (BB*SS*DD)       // 14155776
#define ATTN_ELEMS (BB*HH*SS*SS)   // 127401984
#define SCALE 0.125f

// ---- scratch (static device globals; no runtime allocation) ----
__device__ float g_q[OUT_ELEMS];
__device__ float g_k[OUT_ELEMS];
__device__ float g_v[OUT_ELEMS];
__device__ float g_ctx[OUT_ELEMS];
__device__ float g_xr[OUT_ELEMS];
__device__ float g_wq[DD*DD], g_wk[DD*DD], g_wv[DD*DD], g_wo[DD*DD];
__device__ float g_attn_fallback[ATTN_ELEMS];

// ---------------------------------------------------------------------------
__device__ __forceinline__ float rna_tf32(float x) {
    unsigned u;
    asm("cvt.rna.tf32.f32 %0, %1;" : "=r"(u) : "f"(x));
    return __uint_as_float(u);
}

__device__ __forceinline__ void mma_tf32(float c[4],
    uint32_t a0, uint32_t a1, uint32_t a2, uint32_t a3,
    uint32_t b0, uint32_t b1)
{
    asm volatile(
        "mma.sync.aligned.m16n8k8.row.col.f32.tf32.tf32.f32 "
        "{%0,%1,%2,%3}, {%4,%5,%6,%7}, {%8,%9}, {%0,%1,%2,%3};"
        : "+f"(c[0]), "+f"(c[1]), "+f"(c[2]), "+f"(c[3])
        : "r"(a0), "r"(a1), "r"(a2), "r"(a3), "r"(b0), "r"(b1));
}

__device__ __forceinline__ void cpa16(void* dst, const void* src) {
    uint32_t d = (uint32_t)__cvta_generic_to_shared(dst);
    asm volatile("cp.async.cg.shared.global [%0], [%1], 16;\n"
                 :: "r"(d), "l"(src));
}
#define CP_COMMIT() asm volatile("cp.async.commit_group;\n" ::)
#define CP_WAIT1()  asm volatile("cp.async.wait_group 1;\n" ::)
#define CP_WAIT2()  asm volatile("cp.async.wait_group 2;\n" ::)

// ---------------------------------------------------------------------------
__global__ void round_tf32_kernel(const float* __restrict__ in,
                                  float* __restrict__ out, int n4)
{
    for (int i = blockIdx.x * blockDim.x + threadIdx.x; i < n4;
         i += gridDim.x * blockDim.x) {
        float4 v = ((const float4*)in)[i];
        v.x = rna_tf32(v.x); v.y = rna_tf32(v.y);
        v.z = rna_tf32(v.z); v.w = rna_tf32(v.w);
        ((float4*)out)[i] = v;
    }
}

__global__ void round_w4_kernel(
    const float* __restrict__ w0, const float* __restrict__ w1,
    const float* __restrict__ w2, const float* __restrict__ w3,
    float* __restrict__ o0, float* __restrict__ o1,
    float* __restrict__ o2, float* __restrict__ o3, int n4)
{
    int z = blockIdx.y;
    const float* in = (z == 0) ? w0 : (z == 1) ? w1 : (z == 2) ? w2 : w3;
    float* out      = (z == 0) ? o0 : (z == 1) ? o1 : (z == 2) ? o2 : o3;
    for (int i = blockIdx.x * blockDim.x + threadIdx.x; i < n4;
         i += gridDim.x * blockDim.x) {
        float4 v = ((const float4*)in)[i];
        v.x = rna_tf32(v.x); v.y = rna_tf32(v.y);
        v.z = rna_tf32(v.z); v.w = rna_tf32(v.w);
        ((float4*)out)[i] = v;
    }
}

// ---------------------------------------------------------------------------
// GEMM: C[M,N] = A[M,K] @ W^T + bias.  A,W pre-rounded to tf32.
// RND: round output to tf32 at store (for Q/K/V feeding attention mma).
// BM=128, BN=128, BK=32, 256 threads, 3-stage cp.async pipeline.
// ---------------------------------------------------------------------------
#define GST (2*128*36)   // floats per stage (A+B)

template <bool RND>
__device__ __forceinline__ void gemm_body(
    const float* __restrict__ A, const float* __restrict__ W,
    const float* __restrict__ bias, float* __restrict__ C,
    int N, int K)
{
    extern __shared__ float dsm[];

    const int tid = threadIdx.x;
    const int m0 = blockIdx.y * 128;
    const int n0 = blockIdx.x * 128;
    const int warp = tid >> 5;
    const int lane = tid & 31;
    const int g = lane >> 2;
    const int t = lane & 3;
    const int warpm = warp >> 2;
    const int warpn = warp & 3;

    float acc[4][4][4];
    #pragma unroll
    for (int i = 0; i < 4; i++)
        #pragma unroll
        for (int j = 0; j < 4; j++)
            #pragma unroll
            for (int r = 0; r < 4; r++) acc[i][j][r] = 0.f;

    auto load_stage = [&](int st, int k0) {
        float* as = dsm + st * GST;
        float* bs = as + 128*36;
        #pragma unroll
        for (int i = 0; i < 4; i++) {
            int c = tid + i * 256;
            int row = c >> 3, seg = c & 7;
            cpa16(&as[row*36 + seg*4], &A[(size_t)(m0 + row) * K + k0 + seg*4]);
        }
        #pragma unroll
        for (int i = 0; i < 4; i++) {
            int c = tid + i * 256;
            int row = c >> 3, seg = c & 7;
            cpa16(&bs[row*36 + seg*4], &W[(size_t)(n0 + row) * K + k0 + seg*4]);
        }
    };

    const int iters = K / 32;            // 24
    load_stage(0, 0);  CP_COMMIT();
    load_stage(1, 32); CP_COMMIT();

    for (int it = 0; it < iters; ++it) {
        CP_WAIT1();
        __syncthreads();
        if (it + 2 < iters) load_stage((it + 2) % 3, (it + 2) * 32);
        CP_COMMIT();

        const float* as = dsm + (it % 3) * GST;
        const float* bs = as + 128*36;
        #pragma unroll
        for (int ks = 0; ks < 4; ks++) {
            int k = ks * 8;
            uint32_t af[4][4];
            #pragma unroll
            for (int ms = 0; ms < 4; ms++) {
                const float* p = as + (warpm*64 + ms*16 + g) * 36 + k + t;
                af[ms][0] = __float_as_uint(p[0]);
                af[ms][1] = __float_as_uint(p[8*36]);
                af[ms][2] = __float_as_uint(p[4]);
                af[ms][3] = __float_as_uint(p[8*36 + 4]);
            }
            #pragma unroll
            for (int ns = 0; ns < 4; ns++) {
                const float* p = bs + (warpn*32 + ns*8 + g) * 36 + k + t;
                uint32_t b0 = __float_as_uint(p[0]);
                uint32_t b1 = __float_as_uint(p[4]);
                #pragma unroll
                for (int ms = 0; ms < 4; ms++)
                    mma_tf32(acc[ms][ns], af[ms][0], af[ms][1], af[ms][2],
                             af[ms][3], b0, b1);
            }
        }
    }

    #pragma unroll
    for (int ms = 0; ms < 4; ms++) {
        int row0 = m0 + warpm*64 + ms*16 + g;
        #pragma unroll
        for (int ns = 0; ns < 4; ns++) {
            int col = n0 + warpn*32 + ns*8 + 2*t;
            float b0v = bias[col], b1v = bias[col + 1];
            float2 v0, v1;
            if (RND) {
                v0 = {rna_tf32(acc[ms][ns][0] + b0v), rna_tf32(acc[ms][ns][1] + b1v)};
                v1 = {rna_tf32(acc[ms][ns][2] + b0v), rna_tf32(acc[ms][ns][3] + b1v)};
            } else {
                v0 = {acc[ms][ns][0] + b0v, acc[ms][ns][1] + b1v};
                v1 = {acc[ms][ns][2] + b0v, acc[ms][ns][3] + b1v};
            }
            *(float2*)&C[(size_t)row0 * N + col] = v0;
            *(float2*)&C[(size_t)(row0 + 8) * N + col] = v1;
        }
    }
}

__global__ __launch_bounds__(256) void gemm_qkv(
    const float* __restrict__ A,
    const float* __restrict__ Wq, const float* __restrict__ Wk,
    const float* __restrict__ Wv,
    const float* __restrict__ bq, const float* __restrict__ bk,
    const float* __restrict__ bv,
    float* __restrict__ Cq, float* __restrict__ Ck, float* __restrict__ Cv)
{
    int z = blockIdx.z;
    const float* W    = (z == 0) ? Wq : (z == 1) ? Wk : Wv;
    const float* bias = (z == 0) ? bq : (z == 1) ? bk : bv;
    float*       C    = (z == 0) ? Cq : (z == 1) ? Ck : Cv;
    gemm_body<true>(A, W, bias, C, DD, DD);
}

__global__ __launch_bounds__(256) void gemm_single(
    const float* __restrict__ A, const float* __restrict__ W,
    const float* __restrict__ bias, float* __restrict__ C)
{
    gemm_body<false>(A, W, bias, C, DD, DD);
}

// ---------------------------------------------------------------------------
// Fused attention per (b, h, 32-query tile).
// scores: warp grid (2m x 4n), Q frags in registers.
// softmax: register-resident rows -> 1 strip read + 1 strip write.
// AV: warp grid (Nm,Nn,Nk)=(1,2,4) -> probs read 2x, V read 1x;
//     4 k-partials reduced through smem (strip region reused), ctx float4.
// smem: qs[32][68] + kv[3][32*72] + sc[32][580] = 110592 B -> 2 CTA/SM.
// ---------------------------------------------------------------------------
#define SCQ 68
#define SCK 68
#define VSS 72
#define KVPITCH (32*72)
#define SCS 580
#define QROWS 32
#define NSTAGE (SS/32)  // 18
#define RST 72          // reduction row stride (floats)
#define ATTN_SMEM_FLOATS (QROWS*SCQ + 3*KVPITCH + QROWS*SCS)  // 27648

__global__ __launch_bounds__(256, 2) void attn_fused(
    const float* __restrict__ Q, const float* __restrict__ K,
    const float* __restrict__ V, float* __restrict__ attn,
    float* __restrict__ ctx)
{
    extern __shared__ float smem[];
    float* qs = smem;                         // [32][SCQ]
    float* kv = smem + QROWS*SCQ;             // 3 stage buffers
    float* sc = smem + QROWS*SCQ + 3*KVPITCH; // [32][SCS]; later: red[4][32][RST]

    const int qt = blockIdx.x, h = blockIdx.y, b = blockIdx.z;
    const int s0 = qt * QROWS;
    const int tid = threadIdx.x;
    const int warp = tid >> 5;
    const int lane = tid & 31;
    const int g = lane >> 2, t = lane & 3;
    const int warpm = warp >> 2;   // scores: 0..1
    const int warpn = warp & 3;    // scores: 0..3

    const size_t kvbase = (size_t)b * SS * DD + h * HDD;

    auto load_q = [&]() {
        #pragma unroll
        for (int i = 0; i < 2; i++) {
            int c = tid + i * 256;
            int qi = c >> 4, seg = c & 15;
            cpa16(&qs[qi*SCQ + seg*4],
                  &Q[kvbase + (size_t)(s0 + qi)*DD + seg*4]);
        }
    };
    auto load_k = [&](int st, int kt) {
        float* dst = kv + st * KVPITCH;
        #pragma unroll
        for (int i = 0; i < 2; i++) {
            int c = tid + i * 256;
            int row = c >> 4, seg = c & 15;
            cpa16(&dst[row*SCK + seg*4],
                  &K[kvbase + (size_t)(kt*32 + row)*DD + seg*4]);
        }
    };
    auto load_v = [&](int st, int kt) {
        float* dst = kv + st * KVPITCH;
        #pragma unroll
        for (int i = 0; i < 2; i++) {
            int c = tid + i * 256;
            int row = c >> 4, seg = c & 15;
            cpa16(&dst[row*VSS + seg*4],
                  &V[kvbase + (size_t)(kt*32 + row)*DD + seg*4]);
        }
    };

    load_q();     CP_COMMIT();
    load_k(0, 0); CP_COMMIT();
    load_k(1, 1); CP_COMMIT();

    CP_WAIT2();
    __syncthreads();
    uint32_t qa[8][4];
    #pragma unroll
    for (int kk = 0; kk < 8; kk++) {
        const float* pa = qs + (warpm*16 + g)*SCQ + kk*8 + t;
        qa[kk][0] = __float_as_uint(pa[0]);
        qa[kk][1] = __float_as_uint(pa[8*SCQ]);
        qa[kk][2] = __float_as_uint(pa[4]);
        qa[kk][3] = __float_as_uint(pa[8*SCQ + 4]);
    }

    // ---- scores: QK^T into sc strip, 18 pipelined stages ----
    for (int kt = 0; kt < NSTAGE; kt++) {
        CP_WAIT1();
        __syncthreads();
        if (kt + 2 < NSTAGE) load_k((kt + 2) % 3, kt + 2);
        CP_COMMIT();

        const float* ks = kv + (kt % 3) * KVPITCH;
        float acc[4] = {0.f, 0.f, 0.f, 0.f};
        #pragma unroll
        for (int kk = 0; kk < 8; kk++) {
            const float* pb = ks + (warpn*8 + g)*SCK + kk*8 + t;
            uint32_t b0 = __float_as_uint(pb[0]);
            uint32_t b1 = __float_as_uint(pb[4]);
            mma_tf32(acc, qa[kk][0], qa[kk][1], qa[kk][2], qa[kk][3], b0, b1);
        }

        int row = warpm*16 + g;
        int col = kt*32 + warpn*8 + 2*t;
        float2 v0 = {acc[0]*SCALE, acc[1]*SCALE};
        *(float2*)&sc[row*SCS + col] = v0;
        float2 v1 = {acc[2]*SCALE, acc[3]*SCALE};
        *(float2*)&sc[(row+8)*SCS + col] = v1;
    }
    __syncthreads();

    // prefetch V stages 0,1 -> overlaps softmax
    load_v(0, 0); CP_COMMIT();
    load_v(1, 1); CP_COMMIT();

    // ---- softmax: 8 warps x 4 rows, register-resident ----
    #pragma unroll
    for (int rr = 0; rr < 4; rr++) {
        const int r = warp*4 + rr;
        float ev[18];
        #pragma unroll
        for (int jj = 0; jj < 18; jj++) ev[jj] = sc[r*SCS + lane + 32*jj];
        float mx = ev[0];
        #pragma unroll
        for (int jj = 1; jj < 18; jj++) mx = fmaxf(mx, ev[jj]);
        #pragma unroll
        for (int o = 16; o; o >>= 1) mx = fmaxf(mx, __shfl_xor_sync(0xffffffffu, mx, o));
        float sum = 0.f;
        #pragma unroll
        for (int jj = 0; jj < 18; jj++) {
            ev[jj] = __expf(ev[jj] - mx);
            sum += ev[jj];
        }
        #pragma unroll
        for (int o = 16; o; o >>= 1) sum += __shfl_xor_sync(0xffffffffu, sum, o);
        float inv = 1.f / sum;
        float* dst = attn + (((size_t)b*HH + h)*SS + s0 + r) * (size_t)SS;
        #pragma unroll
        for (int jj = 0; jj < 18; jj++) {
            float p = ev[jj] * inv;
            dst[lane + 32*jj] = p;                      // fp32 attn output
            sc[r*SCS + lane + 32*jj] = rna_tf32(p);     // tf32 for AV mma
        }
    }
    __syncthreads();

    // ---- AV: (Nm,Nn,Nk)=(1,2,4). warp covers rows 0..31, cols wn*32..+31,
    //      k-slice wk*8 within each 32-key stage. 4 k-partials.
    const int wn = warp & 1;
    const int wk = warp >> 1;

    float acc[2][4][4];   // [m-tile][n-tile][frag]
    #pragma unroll
    for (int i = 0; i < 2; i++)
        #pragma unroll
        for (int j = 0; j < 4; j++)
            #pragma unroll
            for (int r = 0; r < 4; r++) acc[i][j][r] = 0.f;

    for (int kt = 0; kt < NSTAGE; kt++) {
        CP_WAIT1();
        __syncthreads();
        if (kt + 2 < NSTAGE) load_v((kt + 2) % 3, kt + 2);
        CP_COMMIT();

        const float* vs = kv + (kt % 3) * KVPITCH;
        const int k = wk * 8;

        uint32_t a[2][4];
        #pragma unroll
        for (int ms = 0; ms < 2; ms++) {
            const float* pa = sc + (ms*16 + g)*SCS + kt*32 + k + t;
            a[ms][0] = __float_as_uint(pa[0]);
            a[ms][1] = __float_as_uint(pa[8*SCS]);
            a[ms][2] = __float_as_uint(pa[4]);
            a[ms][3] = __float_as_uint(pa[8*SCS + 4]);
        }
        #pragma unroll
        for (int ns = 0; ns < 4; ns++) {
            int nb = wn*32 + ns*8;
            uint32_t b0 = __float_as_uint(vs[(k + t)*VSS + nb + g]);
            uint32_t b1 = __float_as_uint(vs[(k + t + 4)*VSS + nb + g]);
            #pragma unroll
            for (int ms = 0; ms < 2; ms++)
                mma_tf32(acc[ms][ns], a[ms][0], a[ms][1], a[ms][2], a[ms][3],
                         b0, b1);
        }
    }

    // ---- reduce 4 k-partials through smem (strip region reused) ----
    __syncthreads();   // all strip reads done before overwrite
    float* red = sc;   // [4][32][RST]
    #pragma unroll
    for (int ms = 0; ms < 2; ms++) {
        #pragma unroll
        for (int ns = 0; ns < 4; ns++) {
            int col = wn*32 + ns*8 + 2*t;
            float2 v0 = {acc[ms][ns][0], acc[ms][ns][1]};
            *(float2*)&red[wk*32*RST + (ms*16 + g)*RST + col] = v0;
            float2 v1 = {acc[ms][ns][2], acc[ms][ns][3]};
            *(float2*)&red[wk*32*RST + (ms*16 + g + 8)*RST + col] = v1;
        }
    }
    __syncthreads();

    // 32x64 ctx: 512 float4 / 256 threads = 2 each
    #pragma unroll
    for (int i = 0; i < 2; i++) {
        int f4 = tid + i*256;
        int row = f4 >> 4, c4 = f4 & 15;
        const float* p0 = red + row*RST + c4*4;
        float4 s0v = *(const float4*)(p0);
        float4 s1v = *(const float4*)(p0 + 32*RST);
        float4 s2v = *(const float4*)(p0 + 64*RST);
        float4 s3v = *(const float4*)(p0 + 96*RST);
        float4 o;
        o.x = rna_tf32(s0v.x + s1v.x + s2v.x + s3v.x);
        o.y = rna_tf32(s0v.y + s1v.y + s2v.y + s3v.y);
        o.z = rna_tf32(s0v.z + s1v.z + s2v.z + s3v.z);
        o.w = rna_tf32(s0v.w + s1v.w + s2v.w + s3v.w);
        *(float4*)&ctx[((size_t)(b*SS + s0 + row))*DD + h*HDD + c4*4] = o;
    }
}

// ===========================================================================
extern "C" void kernel_launch(void* const* d_in, const int* in_sizes, int n_in,
                              void* d_out, int out_size)
{
    const float* x  = (const float*)d_in[0];
    const float* Wq = (const float*)d_in[1];
    const float* bq = (const float*)d_in[2];
    const float* Wk = (const float*)d_in[3];
    const float* bk = (const float*)d_in[4];
    const float* Wv = (const float*)d_in[5];
    const float* bv = (const float*)d_in[6];
    const float* Wo = (const float*)d_in[7];
    const float* bo = (const float*)d_in[8];

    float* out = (float*)d_out;
    float* attn;
    if (out_size >= OUT_ELEMS + ATTN_ELEMS) {
        attn = out + OUT_ELEMS;
    } else {
        void* p; cudaGetSymbolAddress(&p, g_attn_fallback);
        attn = (float*)p;
    }

    float *q, *k, *v, *ctx, *xr, *wq, *wk, *wv, *wo;
    { void* p; cudaGetSymbolAddress(&p, g_q);   q   = (float*)p; }
    { void* p; cudaGetSymbolAddress(&p, g_k);   k   = (float*)p; }
    { void* p; cudaGetSymbolAddress(&p, g_v);   v   = (float*)p; }
    { void* p; cudaGetSymbolAddress(&p, g_ctx); ctx = (float*)p; }
    { void* p; cudaGetSymbolAddress(&p, g_xr);  xr  = (float*)p; }
    { void* p; cudaGetSymbolAddress(&p, g_wq);  wq  = (float*)p; }
    { void* p; cudaGetSymbolAddress(&p, g_wk);  wk  = (float*)p; }
    { void* p; cudaGetSymbolAddress(&p, g_wv);  wv  = (float*)p; }
    { void* p; cudaGetSymbolAddress(&p, g_wo);  wo  = (float*)p; }

    const int gemm_smem = 3 * GST * (int)sizeof(float);          // 110592
    cudaFuncSetAttribute(gemm_qkv,
                         cudaFuncAttributeMaxDynamicSharedMemorySize, gemm_smem);
    cudaFuncSetAttribute(gemm_single,
                         cudaFuncAttributeMaxDynamicSharedMemorySize, gemm_smem);
    const int attn_smem = ATTN_SMEM_FLOATS * (int)sizeof(float); // 110592
    cudaFuncSetAttribute(attn_fused,
                         cudaFuncAttributeMaxDynamicSharedMemorySize, attn_smem);

    // 1) tf32 pre-rounding
    round_tf32_kernel<<<1184, 256>>>(x, xr, OUT_ELEMS/4);
    dim3 gW(288, 4);
    round_w4_kernel<<<gW, 256>>>(Wq, Wk, Wv, Wo, wq, wk, wv, wo, (DD*DD)/4);

    // 2) fused Q/K/V projections (outputs rna-rounded to tf32)
    dim3 gQKV(DD/128, MTOK/128, 3);
    gemm_qkv<<<gQKV, 256, gemm_smem>>>(xr, wq, wk, wv, bq, bk, bv, q, k, v);

    // 3) fused scores + softmax + AV
    dim3 gAttn(SS/QROWS, HH, BB);         // (18, 12, 32)
    attn_fused<<<gAttn, 256, attn_smem>>>(q, k, v, attn, ctx);

    // 4) output projection
    dim3 gO(DD/128, MTOK/128);
    gemm_single<<<gO, 256, gemm_smem>>>(ctx, wo, bo, out);
}

// round 8
// speedup vs baseline: 1.5024x; 1.0579x over previous
#include <cuda_runtime.h>
#include <cstdint>
#include <cstddef>

#define BB 32
#define SS 576
#define DD 768
#define HH 12
#define HDD 64
#define MTOK (BB*SS)               // 18432
#define OUT_ELEMS (BB*SS*DD)       // 14155776
#define ATTN_ELEMS (BB*HH*SS*SS)   // 127401984
#define SCALE 0.125f

// ---- scratch (static device globals; no runtime allocation) ----
__device__ float g_q[OUT_ELEMS];
__device__ float g_k[OUT_ELEMS];
__device__ float g_v[OUT_ELEMS];
__device__ float g_ctx[OUT_ELEMS];
__device__ float g_xr[OUT_ELEMS];
__device__ float g_wq[DD*DD], g_wk[DD*DD], g_wv[DD*DD], g_wo[DD*DD];
__device__ float g_attn_fallback[ATTN_ELEMS];

// ---------------------------------------------------------------------------
__device__ __forceinline__ float rna_tf32(float x) {
    unsigned u;
    asm("cvt.rna.tf32.f32 %0, %1;" : "=r"(u) : "f"(x));
    return __uint_as_float(u);
}

__device__ __forceinline__ void mma_tf32(float c[4],
    uint32_t a0, uint32_t a1, uint32_t a2, uint32_t a3,
    uint32_t b0, uint32_t b1)
{
    asm volatile(
        "mma.sync.aligned.m16n8k8.row.col.f32.tf32.tf32.f32 "
        "{%0,%1,%2,%3}, {%4,%5,%6,%7}, {%8,%9}, {%0,%1,%2,%3};"
        : "+f"(c[0]), "+f"(c[1]), "+f"(c[2]), "+f"(c[3])
        : "r"(a0), "r"(a1), "r"(a2), "r"(a3), "r"(b0), "r"(b1));
}

// ldmatrix.x4 on fp32 data: each 8x8-b16 matrix = 8x4-b32; lane i of the
// result gets b32 element (row i/4, col i%4) -> exactly the tf32 mma frag map.
__device__ __forceinline__ void ldsm_x4(uint32_t& r0, uint32_t& r1,
                                        uint32_t& r2, uint32_t& r3,
                                        const void* p)
{
    uint32_t a = (uint32_t)__cvta_generic_to_shared(p);
    asm volatile("ldmatrix.sync.aligned.m8n8.x4.shared.b16 {%0,%1,%2,%3}, [%4];"
                 : "=r"(r0), "=r"(r1), "=r"(r2), "=r"(r3) : "r"(a));
}

__device__ __forceinline__ void cpa16(void* dst, const void* src) {
    uint32_t d = (uint32_t)__cvta_generic_to_shared(dst);
    asm volatile("cp.async.cg.shared.global [%0], [%1], 16;\n"
                 :: "r"(d), "l"(src));
}
#define CP_COMMIT() asm volatile("cp.async.commit_group;\n" ::)
#define CP_WAIT1()  asm volatile("cp.async.wait_group 1;\n" ::)
#define CP_WAIT2()  asm volatile("cp.async.wait_group 2;\n" ::)

// ---------------------------------------------------------------------------
__global__ void round_tf32_kernel(const float* __restrict__ in,
                                  float* __restrict__ out, int n4)
{
    for (int i = blockIdx.x * blockDim.x + threadIdx.x; i < n4;
         i += gridDim.x * blockDim.x) {
        float4 v = ((const float4*)in)[i];
        v.x = rna_tf32(v.x); v.y = rna_tf32(v.y);
        v.z = rna_tf32(v.z); v.w = rna_tf32(v.w);
        ((float4*)out)[i] = v;
    }
}

__global__ void round_w4_kernel(
    const float* __restrict__ w0, const float* __restrict__ w1,
    const float* __restrict__ w2, const float* __restrict__ w3,
    float* __restrict__ o0, float* __restrict__ o1,
    float* __restrict__ o2, float* __restrict__ o3, int n4)
{
    int z = blockIdx.y;
    const float* in = (z == 0) ? w0 : (z == 1) ? w1 : (z == 2) ? w2 : w3;
    float* out      = (z == 0) ? o0 : (z == 1) ? o1 : (z == 2) ? o2 : o3;
    for (int i = blockIdx.x * blockDim.x + threadIdx.x; i < n4;
         i += gridDim.x * blockDim.x) {
        float4 v = ((const float4*)in)[i];
        v.x = rna_tf32(v.x); v.y = rna_tf32(v.y);
        v.z = rna_tf32(v.z); v.w = rna_tf32(v.w);
        ((float4*)out)[i] = v;
    }
}

// ---------------------------------------------------------------------------
// GEMM: C[M,N] = A[M,K] @ W^T + bias.  A,W pre-rounded to tf32.
// BM=128, BN=128, BK=32, 256 threads, ldmatrix fragment loads,
// 3-stage cp.async pipeline.
// ---------------------------------------------------------------------------
#define GST (2*128*36)   // floats per stage (A+B)

template <bool RND>
__device__ __forceinline__ void gemm_body(
    const float* __restrict__ A, const float* __restrict__ W,
    const float* __restrict__ bias, float* __restrict__ C,
    int N, int K)
{
    extern __shared__ float dsm[];

    const int tid = threadIdx.x;
    const int m0 = blockIdx.y * 128;
    const int n0 = blockIdx.x * 128;
    const int warp = tid >> 5;
    const int lane = tid & 31;
    const int g = lane >> 2;
    const int t = lane & 3;
    const int warpm = warp >> 2;  // 0..1
    const int warpn = warp & 3;   // 0..3

    // ldmatrix lane-offsets (floats)
    // A frag set (16x8 tile): row = lane&15, col = 4*(lane>>4)
    const int laneA = (lane & 15) * 36 + ((lane >> 4) << 2);
    // B pair (two 8-col octets): row = 8*(lane>>4) + (lane&7), col = 4*((lane>>3)&1)
    const int laneB = (((lane >> 4) << 3) + (lane & 7)) * 36 + (((lane >> 3) & 1) << 2);

    float acc[4][4][4];
    #pragma unroll
    for (int i = 0; i < 4; i++)
        #pragma unroll
        for (int j = 0; j < 4; j++)
            #pragma unroll
            for (int r = 0; r < 4; r++) acc[i][j][r] = 0.f;

    auto load_stage = [&](int st, int k0) {
        float* as = dsm + st * GST;
        float* bs = as + 128*36;
        #pragma unroll
        for (int i = 0; i < 4; i++) {
            int c = tid + i * 256;
            int row = c >> 3, seg = c & 7;
            cpa16(&as[row*36 + seg*4], &A[(size_t)(m0 + row) * K + k0 + seg*4]);
        }
        #pragma unroll
        for (int i = 0; i < 4; i++) {
            int c = tid + i * 256;
            int row = c >> 3, seg = c & 7;
            cpa16(&bs[row*36 + seg*4], &W[(size_t)(n0 + row) * K + k0 + seg*4]);
        }
    };

    const int iters = K / 32;            // 24
    load_stage(0, 0);  CP_COMMIT();
    load_stage(1, 32); CP_COMMIT();

    for (int it = 0; it < iters; ++it) {
        CP_WAIT1();
        __syncthreads();
        if (it + 2 < iters) load_stage((it + 2) % 3, (it + 2) * 32);
        CP_COMMIT();

        const float* as = dsm + (it % 3) * GST;
        const float* bs = as + 128*36;
        #pragma unroll
        for (int ks = 0; ks < 4; ks++) {
            int k = ks * 8;
            uint32_t af[4][4];
            #pragma unroll
            for (int ms = 0; ms < 4; ms++)
                ldsm_x4(af[ms][0], af[ms][1], af[ms][2], af[ms][3],
                        as + (warpm*64 + ms*16)*36 + k + laneA);
            #pragma unroll
            for (int pr = 0; pr < 2; pr++) {
                uint32_t b0, b1, b2, b3;   // (b0,b1)=octet 2*pr, (b2,b3)=octet 2*pr+1
                ldsm_x4(b0, b1, b2, b3,
                        bs + (warpn*32 + pr*16)*36 + k + laneB);
                #pragma unroll
                for (int ms = 0; ms < 4; ms++) {
                    mma_tf32(acc[ms][2*pr],   af[ms][0], af[ms][1], af[ms][2],
                             af[ms][3], b0, b1);
                    mma_tf32(acc[ms][2*pr+1], af[ms][0], af[ms][1], af[ms][2],
                             af[ms][3], b2, b3);
                }
            }
        }
    }

    #pragma unroll
    for (int ms = 0; ms < 4; ms++) {
        int row0 = m0 + warpm*64 + ms*16 + g;
        #pragma unroll
        for (int ns = 0; ns < 4; ns++) {
            int col = n0 + warpn*32 + ns*8 + 2*t;
            float b0v = bias[col], b1v = bias[col + 1];
            float2 v0, v1;
            if (RND) {
                v0 = {rna_tf32(acc[ms][ns][0] + b0v), rna_tf32(acc[ms][ns][1] + b1v)};
                v1 = {rna_tf32(acc[ms][ns][2] + b0v), rna_tf32(acc[ms][ns][3] + b1v)};
            } else {
                v0 = {acc[ms][ns][0] + b0v, acc[ms][ns][1] + b1v};
                v1 = {acc[ms][ns][2] + b0v, acc[ms][ns][3] + b1v};
            }
            *(float2*)&C[(size_t)row0 * N + col] = v0;
            *(float2*)&C[(size_t)(row0 + 8) * N + col] = v1;
        }
    }
}

__global__ __launch_bounds__(256) void gemm_qkv(
    const float* __restrict__ A,
    const float* __restrict__ Wq, const float* __restrict__ Wk,
    const float* __restrict__ Wv,
    const float* __restrict__ bq, const float* __restrict__ bk,
    const float* __restrict__ bv,
    float* __restrict__ Cq, float* __restrict__ Ck, float* __restrict__ Cv)
{
    int z = blockIdx.z;
    const float* W    = (z == 0) ? Wq : (z == 1) ? Wk : Wv;
    const float* bias = (z == 0) ? bq : (z == 1) ? bk : bv;
    float*       C    = (z == 0) ? Cq : (z == 1) ? Ck : Cv;
    gemm_body<true>(A, W, bias, C, DD, DD);
}

__global__ __launch_bounds__(256) void gemm_single(
    const float* __restrict__ A, const float* __restrict__ W,
    const float* __restrict__ bias, float* __restrict__ C)
{
    gemm_body<false>(A, W, bias, C, DD, DD);
}

// ---------------------------------------------------------------------------
// Fused attention per (b, h, 32-query tile).
// scores: Q frags in registers, K frags via ldmatrix.x4 (2 k-steps per load).
// softmax: register-resident rows.
// AV: prob frags via ldmatrix.x4; warp grid (Nm,Nn,Nk)=(1,2,4);
//     4 k-partials reduced through smem; ctx float4.
// smem: qs[32][68] + kv[3][32*72] + sc[32][580] = 110592 B -> 2 CTA/SM.
// ---------------------------------------------------------------------------
#define SCQ 68
#define SCK 68
#define VSS 72
#define KVPITCH (32*72)
#define SCS 580
#define QROWS 32
#define NSTAGE (SS/32)  // 18
#define RST 72
#define ATTN_SMEM_FLOATS (QROWS*SCQ + 3*KVPITCH + QROWS*SCS)  // 27648

__global__ __launch_bounds__(256, 2) void attn_fused(
    const float* __restrict__ Q, const float* __restrict__ K,
    const float* __restrict__ V, float* __restrict__ attn,
    float* __restrict__ ctx)
{
    extern __shared__ float smem[];
    float* qs = smem;                         // [32][SCQ]
    float* kv = smem + QROWS*SCQ;             // 3 stage buffers
    float* sc = smem + QROWS*SCQ + 3*KVPITCH; // [32][SCS]; later red[4][32][RST]

    const int qt = blockIdx.x, h = blockIdx.y, b = blockIdx.z;
    const int s0 = qt * QROWS;
    const int tid = threadIdx.x;
    const int warp = tid >> 5;
    const int lane = tid & 31;
    const int g = lane >> 2, t = lane & 3;
    const int warpm = warp >> 2;   // scores: 0..1
    const int warpn = warp & 3;    // scores: 0..3

    const size_t kvbase = (size_t)b * SS * DD + h * HDD;

    auto load_q = [&]() {
        #pragma unroll
        for (int i = 0; i < 2; i++) {
            int c = tid + i * 256;
            int qi = c >> 4, seg = c & 15;
            cpa16(&qs[qi*SCQ + seg*4],
                  &Q[kvbase + (size_t)(s0 + qi)*DD + seg*4]);
        }
    };
    auto load_k = [&](int st, int kt) {
        float* dst = kv + st * KVPITCH;
        #pragma unroll
        for (int i = 0; i < 2; i++) {
            int c = tid + i * 256;
            int row = c >> 4, seg = c & 15;
            cpa16(&dst[row*SCK + seg*4],
                  &K[kvbase + (size_t)(kt*32 + row)*DD + seg*4]);
        }
    };
    auto load_v = [&](int st, int kt) {
        float* dst = kv + st * KVPITCH;
        #pragma unroll
        for (int i = 0; i < 2; i++) {
            int c = tid + i * 256;
            int row = c >> 4, seg = c & 15;
            cpa16(&dst[row*VSS + seg*4],
                  &V[kvbase + (size_t)(kt*32 + row)*DD + seg*4]);
        }
    };

    load_q();     CP_COMMIT();
    load_k(0, 0); CP_COMMIT();
    load_k(1, 1); CP_COMMIT();

    CP_WAIT2();
    __syncthreads();
    uint32_t qa[8][4];
    #pragma unroll
    for (int kk = 0; kk < 8; kk++) {
        const float* pa = qs + (warpm*16 + g)*SCQ + kk*8 + t;
        qa[kk][0] = __float_as_uint(pa[0]);
        qa[kk][1] = __float_as_uint(pa[8*SCQ]);
        qa[kk][2] = __float_as_uint(pa[4]);
        qa[kk][3] = __float_as_uint(pa[8*SCQ + 4]);
    }

    // K-frag ldmatrix lane offset: x4 covers (n0..7) x (k..k+15) = 2 k-steps
    // row = lane&7, col = 4*(lane>>3)
    const int laneKB = (lane & 7) * SCK + ((lane >> 3) << 2);
    // AV prob-frag lane offset: row = lane&15, col = 4*(lane>>4)
    const int laneAS = (lane & 15) * SCS + ((lane >> 4) << 2);

    // ---- scores: QK^T into sc strip, 18 pipelined stages ----
    for (int kt = 0; kt < NSTAGE; kt++) {
        CP_WAIT1();
        __syncthreads();
        if (kt + 2 < NSTAGE) load_k((kt + 2) % 3, kt + 2);
        CP_COMMIT();

        const float* ks = kv + (kt % 3) * KVPITCH;
        float acc[4] = {0.f, 0.f, 0.f, 0.f};
        #pragma unroll
        for (int kk2 = 0; kk2 < 4; kk2++) {
            uint32_t b0, b1, b2, b3;  // (b0,b1) k-step 2*kk2, (b2,b3) 2*kk2+1
            ldsm_x4(b0, b1, b2, b3,
                    ks + warpn*8*SCK + kk2*16 + laneKB);
            mma_tf32(acc, qa[2*kk2][0], qa[2*kk2][1], qa[2*kk2][2],
                     qa[2*kk2][3], b0, b1);
            mma_tf32(acc, qa[2*kk2+1][0], qa[2*kk2+1][1], qa[2*kk2+1][2],
                     qa[2*kk2+1][3], b2, b3);
        }

        int row = warpm*16 + g;
        int col = kt*32 + warpn*8 + 2*t;
        float2 v0 = {acc[0]*SCALE, acc[1]*SCALE};
        *(float2*)&sc[row*SCS + col] = v0;
        float2 v1 = {acc[2]*SCALE, acc[3]*SCALE};
        *(float2*)&sc[(row+8)*SCS + col] = v1;
    }
    __syncthreads();

    // prefetch V stages 0,1 -> overlaps softmax
    load_v(0, 0); CP_COMMIT();
    load_v(1, 1); CP_COMMIT();

    // ---- softmax: 8 warps x 4 rows, register-resident ----
    #pragma unroll
    for (int rr = 0; rr < 4; rr++) {
        const int r = warp*4 + rr;
        float ev[18];
        #pragma unroll
        for (int jj = 0; jj < 18; jj++) ev[jj] = sc[r*SCS + lane + 32*jj];
        float mx = ev[0];
        #pragma unroll
        for (int jj = 1; jj < 18; jj++) mx = fmaxf(mx, ev[jj]);
        #pragma unroll
        for (int o = 16; o; o >>= 1) mx = fmaxf(mx, __shfl_xor_sync(0xffffffffu, mx, o));
        float sum = 0.f;
        #pragma unroll
        for (int jj = 0; jj < 18; jj++) {
            ev[jj] = __expf(ev[jj] - mx);
            sum += ev[jj];
        }
        #pragma unroll
        for (int o = 16; o; o >>= 1) sum += __shfl_xor_sync(0xffffffffu, sum, o);
        float inv = 1.f / sum;
        float* dst = attn + (((size_t)b*HH + h)*SS + s0 + r) * (size_t)SS;
        #pragma unroll
        for (int jj = 0; jj < 18; jj++) {
            float p = ev[jj] * inv;
            dst[lane + 32*jj] = p;
            sc[r*SCS + lane + 32*jj] = rna_tf32(p);
        }
    }
    __syncthreads();

    // ---- AV: (Nm,Nn,Nk)=(1,2,4) ----
    const int wn = warp & 1;
    const int wk = warp >> 1;

    float acc[2][4][4];
    #pragma unroll
    for (int i = 0; i < 2; i++)
        #pragma unroll
        for (int j = 0; j < 4; j++)
            #pragma unroll
            for (int r = 0; r < 4; r++) acc[i][j][r] = 0.f;

    for (int kt = 0; kt < NSTAGE; kt++) {
        CP_WAIT1();
        __syncthreads();
        if (kt + 2 < NSTAGE) load_v((kt + 2) % 3, kt + 2);
        CP_COMMIT();

        const float* vs = kv + (kt % 3) * KVPITCH;
        const int k = wk * 8;

        uint32_t a[2][4];
        #pragma unroll
        for (int ms = 0; ms < 2; ms++)
            ldsm_x4(a[ms][0], a[ms][1], a[ms][2], a[ms][3],
                    sc + ms*16*SCS + kt*32 + k + laneAS);
        #pragma unroll
        for (int ns = 0; ns < 4; ns++) {
            int nb = wn*32 + ns*8;
            uint32_t b0 = __float_as_uint(vs[(k + t)*VSS + nb + g]);
            uint32_t b1 = __float_as_uint(vs[(k + t + 4)*VSS + nb + g]);
            #pragma unroll
            for (int ms = 0; ms < 2; ms++)
                mma_tf32(acc[ms][ns], a[ms][0], a[ms][1], a[ms][2], a[ms][3],
                         b0, b1);
        }
    }

    // ---- reduce 4 k-partials through smem ----
    __syncthreads();
    float* red = sc;   // [4][32][RST]
    #pragma unroll
    for (int ms = 0; ms < 2; ms++) {
        #pragma unroll
        for (int ns = 0; ns < 4; ns++) {
            int col = wn*32 + ns*8 + 2*t;
            float2 v0 = {acc[ms][ns][0], acc[ms][ns][1]};
            *(float2*)&red[wk*32*RST + (ms*16 + g)*RST + col] = v0;
            float2 v1 = {acc[ms][ns][2], acc[ms][ns][3]};
            *(float2*)&red[wk*32*RST + (ms*16 + g + 8)*RST + col] = v1;
        }
    }
    __syncthreads();

    #pragma unroll
    for (int i = 0; i < 2; i++) {
        int f4 = tid + i*256;
        int row = f4 >> 4, c4 = f4 & 15;
        const float* p0 = red + row*RST + c4*4;
        float4 s0v = *(const float4*)(p0);
        float4 s1v = *(const float4*)(p0 + 32*RST);
        float4 s2v = *(const float4*)(p0 + 64*RST);
        float4 s3v = *(const float4*)(p0 + 96*RST);
        float4 o;
        o.x = rna_tf32(s0v.x + s1v.x + s2v.x + s3v.x);
        o.y = rna_tf32(s0v.y + s1v.y + s2v.y + s3v.y);
        o.z = rna_tf32(s0v.z + s1v.z + s2v.z + s3v.z);
        o.w = rna_tf32(s0v.w + s1v.w + s2v.w + s3v.w);
        *(float4*)&ctx[((size_t)(b*SS + s0 + row))*DD + h*HDD + c4*4] = o;
    }
}

// ===========================================================================
extern "C" void kernel_launch(void* const* d_in, const int* in_sizes, int n_in,
                              void* d_out, int out_size)
{
    const float* x  = (const float*)d_in[0];
    const float* Wq = (const float*)d_in[1];
    const float* bq = (const float*)d_in[2];
    const float* Wk = (const float*)d_in[3];
    const float* bk = (const float*)d_in[4];
    const float* Wv = (const float*)d_in[5];
    const float* bv = (const float*)d_in[6];
    const float* Wo = (const float*)d_in[7];
    const float* bo = (const float*)d_in[8];

    float* out = (float*)d_out;
    float* attn;
    if (out_size >= OUT_ELEMS + ATTN_ELEMS) {
        attn = out + OUT_ELEMS;
    } else {
        void* p; cudaGetSymbolAddress(&p, g_attn_fallback);
        attn = (float*)p;
    }

    float *q, *k, *v, *ctx, *xr, *wq, *wk, *wv, *wo;
    { void* p; cudaGetSymbolAddress(&p, g_q);   q   = (float*)p; }
    { void* p; cudaGetSymbolAddress(&p, g_k);   k   = (float*)p; }
    { void* p; cudaGetSymbolAddress(&p, g_v);   v   = (float*)p; }
    { void* p; cudaGetSymbolAddress(&p, g_ctx); ctx = (float*)p; }
    { void* p; cudaGetSymbolAddress(&p, g_xr);  xr  = (float*)p; }
    { void* p; cudaGetSymbolAddress(&p, g_wq);  wq  = (float*)p; }
    { void* p; cudaGetSymbolAddress(&p, g_wk);  wk  = (float*)p; }
    { void* p; cudaGetSymbolAddress(&p, g_wv);  wv  = (float*)p; }
    { void* p; cudaGetSymbolAddress(&p, g_wo);  wo  = (float*)p; }

    const int gemm_smem = 3 * GST * (int)sizeof(float);          // 110592
    cudaFuncSetAttribute(gemm_qkv,
                         cudaFuncAttributeMaxDynamicSharedMemorySize, gemm_smem);
    cudaFuncSetAttribute(gemm_single,
                         cudaFuncAttributeMaxDynamicSharedMemorySize, gemm_smem);
    const int attn_smem = ATTN_SMEM_FLOATS * (int)sizeof(float); // 110592
    cudaFuncSetAttribute(attn_fused,
                         cudaFuncAttributeMaxDynamicSharedMemorySize, attn_smem);

    // 1) tf32 pre-rounding
    round_tf32_kernel<<<1184, 256>>>(x, xr, OUT_ELEMS/4);
    dim3 gW(288, 4);
    round_w4_kernel<<<gW, 256>>>(Wq, Wk, Wv, Wo, wq, wk, wv, wo, (DD*DD)/4);

    // 2) fused Q/K/V projections (outputs rna-rounded to tf32)
    dim3 gQKV(DD/128, MTOK/128, 3);
    gemm_qkv<<<gQKV, 256, gemm_smem>>>(xr, wq, wk, wv, bq, bk, bv, q, k, v);

    // 3) fused scores + softmax + AV
    dim3 gAttn(SS/QROWS, HH, BB);         // (18, 12, 32)
    attn_fused<<<gAttn, 256, attn_smem>>>(q, k, v, attn, ctx);

    // 4) output projection
    dim3 gO(DD/128, MTOK/128);
    gemm_single<<<gO, 256, gemm_smem>>>(ctx, wo, bo, out);
}